// round 1
// baseline (speedup 1.0000x reference)
#include <cuda_runtime.h>
#include <math.h>

// Problem constants
#define Bsz 2
#define Lx  2048
#define Cx  1024
#define Hx  16
#define Dx  64
#define Mrows (Bsz*Lx)      // 4096

// ---------------- scratch (__device__ globals: alloc-free) ----------------
__device__ float g_h  [Mrows * Cx];        // LN output (reused)
__device__ float g_qkv[Mrows * 3 * Cx];    // QKV
__device__ float g_y  [Mrows * Cx];        // attention output
__device__ float g_x1 [Mrows * Cx];        // x + attn-proj
__device__ float g_fc [Mrows * 4 * Cx];    // gelu(fc) output

// ---------------- LayerNorm: one block per row, 256 threads ----------------
__global__ __launch_bounds__(256) void ln_kernel(const float* __restrict__ x,
                                                 const float* __restrict__ w,
                                                 const float* __restrict__ b,
                                                 float* __restrict__ out)
{
    int row = blockIdx.x;
    int t   = threadIdx.x;
    const float4* xr = (const float4*)(x + (size_t)row * Cx);
    float4 v = xr[t];
    float s  = v.x + v.y + v.z + v.w;
    float sq = v.x*v.x + v.y*v.y + v.z*v.z + v.w*v.w;
    #pragma unroll
    for (int o = 16; o > 0; o >>= 1) {
        s  += __shfl_xor_sync(0xffffffffu, s,  o);
        sq += __shfl_xor_sync(0xffffffffu, sq, o);
    }
    __shared__ float ss[8], ssq[8];
    int wid = t >> 5, lane = t & 31;
    if (lane == 0) { ss[wid] = s; ssq[wid] = sq; }
    __syncthreads();
    float tot = 0.f, totq = 0.f;
    #pragma unroll
    for (int i = 0; i < 8; i++) { tot += ss[i]; totq += ssq[i]; }
    float mean = tot * (1.0f / Cx);
    float var  = totq * (1.0f / Cx) - mean * mean;
    float rstd = rsqrtf(var + 1e-5f);
    const float4 wv = ((const float4*)w)[t];
    const float4 bv = ((const float4*)b)[t];
    float4 o;
    o.x = (v.x - mean) * rstd * wv.x + bv.x;
    o.y = (v.y - mean) * rstd * wv.y + bv.y;
    o.z = (v.z - mean) * rstd * wv.z + bv.z;
    o.w = (v.w - mean) * rstd * wv.w + bv.w;
    ((float4*)(out + (size_t)row * Cx))[t] = o;
}

// ---------------- GELU ----------------
__device__ __forceinline__ float gelu_f(float x) {
    float x3 = x * x * x;
    float t  = tanhf(0.7978845608028654f * (x + 0.044715f * x3));
    return 0.5f * x * (1.0f + t);
}

// ---------------- GEMM: out[M,N] = A[M,K] @ W[K,N] + bias (+epilogue) ------
// EPI: 0 = bias, 1 = bias + gelu, 2 = bias + residual
#define BM 128
#define BN 128
#define BK 16

template<int EPI>
__global__ __launch_bounds__(256) void gemm_kernel(
    const float* __restrict__ A, const float* __restrict__ W,
    const float* __restrict__ bias, const float* __restrict__ res,
    float* __restrict__ out, int M, int N, int K)
{
    __shared__ float As[BK][BM];
    __shared__ float Bs[BK][BN];

    int tid = threadIdx.x;
    int bm  = blockIdx.y * BM;
    int bn  = blockIdx.x * BN;
    int tx  = tid & 15;       // 0..15
    int ty  = tid >> 4;       // 0..15

    float acc[8][8];
    #pragma unroll
    for (int i = 0; i < 8; i++)
        #pragma unroll
        for (int j = 0; j < 8; j++) acc[i][j] = 0.f;

    for (int k0 = 0; k0 < K; k0 += BK) {
        __syncthreads();
        // load tiles: 512 float4 each, 2 per thread
        #pragma unroll
        for (int u = 0; u < 2; u++) {
            int f   = tid * 2 + u;
            int row = f >> 2;          // 0..127
            int kq  = f & 3;           // 0..3
            float4 av = *(const float4*)(A + (size_t)(bm + row) * K + k0 + kq * 4);
            As[kq*4+0][row] = av.x;
            As[kq*4+1][row] = av.y;
            As[kq*4+2][row] = av.z;
            As[kq*4+3][row] = av.w;

            int g    = tid * 2 + u;
            int brow = g >> 5;         // 0..15
            int bcol = (g & 31) * 4;   // 0..124
            *(float4*)&Bs[brow][bcol] =
                *(const float4*)(W + (size_t)(k0 + brow) * N + bn + bcol);
        }
        __syncthreads();

        #pragma unroll
        for (int kk = 0; kk < BK; kk++) {
            float a[8], bb[8];
            *(float4*)&a[0]  = *(const float4*)&As[kk][ty * 8];
            *(float4*)&a[4]  = *(const float4*)&As[kk][ty * 8 + 4];
            *(float4*)&bb[0] = *(const float4*)&Bs[kk][tx * 8];
            *(float4*)&bb[4] = *(const float4*)&Bs[kk][tx * 8 + 4];
            #pragma unroll
            for (int i = 0; i < 8; i++)
                #pragma unroll
                for (int j = 0; j < 8; j++)
                    acc[i][j] += a[i] * bb[j];
        }
    }

    // epilogue
    #pragma unroll
    for (int i = 0; i < 8; i++) {
        int row = bm + ty * 8 + i;
        #pragma unroll
        for (int j = 0; j < 8; j += 4) {
            int col = bn + tx * 8 + j;
            float4 bv = *(const float4*)(bias + col);
            float4 c;
            c.x = acc[i][j+0] + bv.x;
            c.y = acc[i][j+1] + bv.y;
            c.z = acc[i][j+2] + bv.z;
            c.w = acc[i][j+3] + bv.w;
            if (EPI == 1) {
                c.x = gelu_f(c.x); c.y = gelu_f(c.y);
                c.z = gelu_f(c.z); c.w = gelu_f(c.w);
            }
            if (EPI == 2) {
                float4 rv = *(const float4*)(res + (size_t)row * N + col);
                c.x += rv.x; c.y += rv.y; c.z += rv.z; c.w += rv.w;
            }
            *(float4*)(out + (size_t)row * N + col) = c;
        }
    }
}

// ---------------- Causal flash attention --------------------------------
// grid (L/64, B*H), 64 threads/block, 1 thread = 1 query row.
// qkv layout: row (b*L+l) of 3072 floats; q at h*64, k at C+h*64, v at 2C+h*64
__global__ __launch_bounds__(64) void attn_kernel(const float* __restrict__ qkv,
                                                  float* __restrict__ y)
{
    __shared__ float Ks[64][68];
    __shared__ float Vs[64][68];
    int qt  = blockIdx.x;
    int bh  = blockIdx.y;
    int b   = bh >> 4;
    int h   = bh & 15;
    int tid = threadIdx.x;
    int qi  = qt * 64 + tid;

    size_t base = (size_t)b * Lx * 3072;
    const float4* qp = (const float4*)(qkv + base + (size_t)qi * 3072 + h * 64);
    float q[64];
    #pragma unroll
    for (int i = 0; i < 16; i++) {
        float4 t = qp[i];
        q[4*i]   = t.x * 0.125f;  // 1/sqrt(64)
        q[4*i+1] = t.y * 0.125f;
        q[4*i+2] = t.z * 0.125f;
        q[4*i+3] = t.w * 0.125f;
    }
    float acc[64];
    #pragma unroll
    for (int i = 0; i < 64; i++) acc[i] = 0.f;
    float mval = -1e30f, l = 0.f;

    int ktiles = qt + 1;   // uniform within block (causal bound)
    for (int kt = 0; kt < ktiles; kt++) {
        int k0 = kt * 64;
        __syncthreads();
        {
            const float4* kp = (const float4*)(qkv + base + (size_t)(k0 + tid) * 3072 + Cx     + h * 64);
            const float4* vp = (const float4*)(qkv + base + (size_t)(k0 + tid) * 3072 + 2*Cx   + h * 64);
            float4* kd = (float4*)&Ks[tid][0];
            float4* vd = (float4*)&Vs[tid][0];
            #pragma unroll
            for (int i = 0; i < 16; i++) { kd[i] = kp[i]; vd[i] = vp[i]; }
        }
        __syncthreads();

        #pragma unroll 1
        for (int j0 = 0; j0 < 64; j0 += 16) {
            if (k0 + j0 > qi) break;  // chunk fully masked (does not skip syncs)
            float s[16];
            #pragma unroll
            for (int jj = 0; jj < 16; jj++) {
                const float4* kr = (const float4*)&Ks[j0 + jj][0];
                float d0 = 0.f, d1 = 0.f, d2 = 0.f, d3 = 0.f;
                #pragma unroll
                for (int i = 0; i < 16; i++) {
                    float4 kv = kr[i];
                    d0 += q[4*i]   * kv.x;
                    d1 += q[4*i+1] * kv.y;
                    d2 += q[4*i+2] * kv.z;
                    d3 += q[4*i+3] * kv.w;
                }
                float dot = (d0 + d1) + (d2 + d3);
                s[jj] = (k0 + j0 + jj <= qi) ? dot : -1e30f;
            }
            float cmax = s[0];
            #pragma unroll
            for (int jj = 1; jj < 16; jj++) cmax = fmaxf(cmax, s[jj]);
            float mnew = fmaxf(mval, cmax);
            float corr = __expf(mval - mnew);
            mval = mnew;
            l *= corr;
            #pragma unroll
            for (int i = 0; i < 64; i++) acc[i] *= corr;
            #pragma unroll
            for (int jj = 0; jj < 16; jj++) {
                float p = __expf(s[jj] - mval);
                l += p;
                const float4* vr = (const float4*)&Vs[j0 + jj][0];
                #pragma unroll
                for (int i = 0; i < 16; i++) {
                    float4 vv = vr[i];
                    acc[4*i]   += p * vv.x;
                    acc[4*i+1] += p * vv.y;
                    acc[4*i+2] += p * vv.z;
                    acc[4*i+3] += p * vv.w;
                }
            }
        }
    }

    float inv = 1.0f / l;
    float4* yp = (float4*)(y + ((size_t)(b * Lx + qi)) * Cx + h * 64);
    #pragma unroll
    for (int i = 0; i < 16; i++) {
        float4 o;
        o.x = acc[4*i]   * inv;
        o.y = acc[4*i+1] * inv;
        o.z = acc[4*i+2] * inv;
        o.w = acc[4*i+3] * inv;
        yp[i] = o;
    }
}

// ---------------- launcher ----------------
extern "C" void kernel_launch(void* const* d_in, const int* in_sizes, int n_in,
                              void* d_out, int out_size)
{
    const float* x      = (const float*)d_in[0];
    const float* ln1_w  = (const float*)d_in[1];
    const float* ln1_b  = (const float*)d_in[2];
    const float* w_attn = (const float*)d_in[3];
    const float* b_attn = (const float*)d_in[4];
    const float* w_proj = (const float*)d_in[5];
    const float* b_proj = (const float*)d_in[6];
    const float* ln2_w  = (const float*)d_in[7];
    const float* ln2_b  = (const float*)d_in[8];
    const float* w_fc   = (const float*)d_in[9];
    const float* b_fc   = (const float*)d_in[10];
    const float* w_fc2  = (const float*)d_in[11];
    const float* b_fc2  = (const float*)d_in[12];
    float* out = (float*)d_out;

    void *ph, *pqkv, *py, *px1, *pfc;
    cudaGetSymbolAddress(&ph,   g_h);
    cudaGetSymbolAddress(&pqkv, g_qkv);
    cudaGetSymbolAddress(&py,   g_y);
    cudaGetSymbolAddress(&px1,  g_x1);
    cudaGetSymbolAddress(&pfc,  g_fc);
    float* h   = (float*)ph;
    float* qkv = (float*)pqkv;
    float* y   = (float*)py;
    float* x1  = (float*)px1;
    float* fc  = (float*)pfc;

    // 1) h = LN1(x)
    ln_kernel<<<Mrows, 256>>>(x, ln1_w, ln1_b, h);
    // 2) qkv = h @ w_attn + b_attn                       [4096, 3072]
    gemm_kernel<0><<<dim3(3*Cx/BN, Mrows/BM), 256>>>(h, w_attn, b_attn, nullptr, qkv,
                                                     Mrows, 3*Cx, Cx);
    // 3) y = causal_attention(qkv)                       [4096, 1024]
    attn_kernel<<<dim3(Lx/64, Bsz*Hx), 64>>>(qkv, y);
    // 4) x1 = x + y @ w_proj + b_proj
    gemm_kernel<2><<<dim3(Cx/BN, Mrows/BM), 256>>>(y, w_proj, b_proj, x, x1,
                                                   Mrows, Cx, Cx);
    // 5) h = LN2(x1)
    ln_kernel<<<Mrows, 256>>>(x1, ln2_w, ln2_b, h);
    // 6) fc = gelu(h @ w_fc + b_fc)                      [4096, 4096]
    gemm_kernel<1><<<dim3(4*Cx/BN, Mrows/BM), 256>>>(h, w_fc, b_fc, nullptr, fc,
                                                     Mrows, 4*Cx, Cx);
    // 7) out = x1 + fc @ w_fc2 + b_fc2
    gemm_kernel<2><<<dim3(Cx/BN, Mrows/BM), 256>>>(fc, w_fc2, b_fc2, x1, out,
                                                   Mrows, Cx, 4*Cx);
}

// round 4
// speedup vs baseline: 1.8529x; 1.8529x over previous
#include <cuda_runtime.h>
#include <cuda_bf16.h>
#include <math.h>
#include <stdint.h>

// Problem constants
#define Bsz 2
#define Lx  2048
#define Cx  1024
#define Hx  16
#define Dx  64
#define Mrows (Bsz*Lx)      // 4096

// ---------------- scratch (__device__ globals: alloc-free) ----------------
__device__ float g_qkv[Mrows * 3 * Cx];
__device__ float g_x1 [Mrows * Cx];

__device__ __nv_bfloat16 g_h_hi [Mrows * Cx];
__device__ __nv_bfloat16 g_h_lo [Mrows * Cx];
__device__ __nv_bfloat16 g_y_hi [Mrows * Cx];
__device__ __nv_bfloat16 g_y_lo [Mrows * Cx];
__device__ __nv_bfloat16 g_fc_hi[Mrows * 4 * Cx];
__device__ __nv_bfloat16 g_fc_lo[Mrows * 4 * Cx];

__device__ __nv_bfloat16 g_wa_hi [Cx * 3 * Cx];
__device__ __nv_bfloat16 g_wa_lo [Cx * 3 * Cx];
__device__ __nv_bfloat16 g_wp_hi [Cx * Cx];
__device__ __nv_bfloat16 g_wp_lo [Cx * Cx];
__device__ __nv_bfloat16 g_wf_hi [Cx * 4 * Cx];
__device__ __nv_bfloat16 g_wf_lo [Cx * 4 * Cx];
__device__ __nv_bfloat16 g_wf2_hi[4 * Cx * Cx];
__device__ __nv_bfloat16 g_wf2_lo[4 * Cx * Cx];

// ================= helpers ==========================
__device__ __forceinline__ uint32_t smem_u32(const void* p) {
    uint32_t a;
    asm("{ .reg .u64 t; cvta.to.shared.u64 t, %1; cvt.u32.u64 %0, t; }"
        : "=r"(a) : "l"(p));
    return a;
}
__device__ __forceinline__ float hi_part(float x) {
    return __uint_as_float(__float_as_uint(x) & 0xFFFF0000u);
}
// pack hi bf16 of (a,b) into one u32 (a in low half)
__device__ __forceinline__ uint32_t pack_hi(float a, float b) {
    return __byte_perm(__float_as_uint(a), __float_as_uint(b), 0x7632);
}
__device__ __forceinline__ uint32_t pack_lo(float a, float b) {
    __nv_bfloat162 p = __floats2bfloat162_rn(a - hi_part(a), b - hi_part(b));
    return *(uint32_t*)&p;
}

__device__ __forceinline__ void cp16(uint32_t dst, const void* src) {
    asm volatile("cp.async.cg.shared.global [%0], [%1], 16;"
                 :: "r"(dst), "l"(src));
}
#define CP_COMMIT() asm volatile("cp.async.commit_group;" ::: "memory")
#define CP_WAIT2()  asm volatile("cp.async.wait_group 2;" ::: "memory")

__device__ __forceinline__ void ldsm4(uint32_t (&r)[4], uint32_t addr) {
    asm volatile("ldmatrix.sync.aligned.m8n8.x4.shared.b16 {%0,%1,%2,%3}, [%4];"
                 : "=r"(r[0]), "=r"(r[1]), "=r"(r[2]), "=r"(r[3]) : "r"(addr));
}
__device__ __forceinline__ void ldsm4t(uint32_t (&r)[4], uint32_t addr) {
    asm volatile("ldmatrix.sync.aligned.m8n8.x4.trans.shared.b16 {%0,%1,%2,%3}, [%4];"
                 : "=r"(r[0]), "=r"(r[1]), "=r"(r[2]), "=r"(r[3]) : "r"(addr));
}
__device__ __forceinline__ void mma_bf16(float (&c)[4], const uint32_t (&a)[4],
                                         uint32_t b0, uint32_t b1) {
    asm volatile(
        "mma.sync.aligned.m16n8k16.row.col.f32.bf16.bf16.f32 "
        "{%0,%1,%2,%3},{%4,%5,%6,%7},{%8,%9},{%0,%1,%2,%3};"
        : "+f"(c[0]), "+f"(c[1]), "+f"(c[2]), "+f"(c[3])
        : "r"(a[0]), "r"(a[1]), "r"(a[2]), "r"(a[3]), "r"(b0), "r"(b1));
}

__device__ __forceinline__ float gelu_f(float x) {
    float x3 = x * x * x;
    float t  = tanhf(0.7978845608028654f * (x + 0.044715f * x3));
    return 0.5f * x * (1.0f + t);
}

// ---------------- weight fp32 -> bf16 hi/lo (per-launch pre-pass) ---------
__global__ __launch_bounds__(256) void conv_w(const float* __restrict__ w,
                                              __nv_bfloat16* __restrict__ hi,
                                              __nv_bfloat16* __restrict__ lo,
                                              int n4)
{
    int i = blockIdx.x * 256 + threadIdx.x;
    if (i >= n4) return;
    float4 v = ((const float4*)w)[i];
    uint2 h = make_uint2(pack_hi(v.x, v.y), pack_hi(v.z, v.w));
    uint2 l = make_uint2(pack_lo(v.x, v.y), pack_lo(v.z, v.w));
    ((uint2*)hi)[i] = h;
    ((uint2*)lo)[i] = l;
}

// =========================================================================
// split-bf16 GEMM via mma.sync: out = A[M,K] @ W[K,N] + bias (+epilogue)
// A given as bf16 hi/lo [M,K] row-major; W as bf16 hi/lo [K,N] row-major.
// EPI: 0 = bias -> fp32 out
//      1 = bias+gelu -> bf16 hi/lo out only
//      2 = bias+residual -> fp32 out
// CTA 128x128, 8 warps (warp tile 64x32), BK=32, 3-stage cp.async pipeline.
// =========================================================================
#define BKC 32
#define A_STRIDE 80          // 64B data + 16B pad  (conflict-free ldmatrix)
#define B_STRIDE 272         // 256B data + 16B pad (conflict-free ldmatrix.trans)
#define SZ_A (128 * A_STRIDE)          // 10240
#define SZ_B (BKC * B_STRIDE)          // 8704
#define OFF_AL SZ_A                    // 10240
#define OFF_BH (2 * SZ_A)              // 20480
#define OFF_BL (2 * SZ_A + SZ_B)       // 29184
#define STAGE_BYTES (2 * SZ_A + 2 * SZ_B)   // 37888
#define GEMM_SMEM (3 * STAGE_BYTES)         // 113664

template<int EPI>
__global__ __launch_bounds__(256) void mma_gemm(
    const __nv_bfloat16* __restrict__ Ahi, const __nv_bfloat16* __restrict__ Alo,
    const __nv_bfloat16* __restrict__ Whi, const __nv_bfloat16* __restrict__ Wlo,
    const float* __restrict__ bias, const float* __restrict__ res,
    float* __restrict__ outf,
    __nv_bfloat16* __restrict__ out_hi, __nv_bfloat16* __restrict__ out_lo,
    int M, int N, int K)
{
    extern __shared__ char smem_raw[];
    const uint32_t sm = smem_u32(smem_raw);

    const int tid  = threadIdx.x;
    const int wid  = tid >> 5;
    const int lane = tid & 31;
    const int bm   = blockIdx.y * 128;
    const int bn   = blockIdx.x * 128;
    const int wm   = wid >> 2;          // 0..1
    const int wn   = wid & 3;           // 0..3
    const int nch  = K >> 5;

    float acc[4][4][4];
    #pragma unroll
    for (int i = 0; i < 4; i++)
        #pragma unroll
        for (int j = 0; j < 4; j++)
            #pragma unroll
            for (int q = 0; q < 4; q++) acc[i][j][q] = 0.f;

    // ---- async stage loader: 2048 x 16B, 8 per thread ----
    auto load_stage = [&](int c) {
        if (c < nch) {
            const int s  = c - (c / 3) * 3;
            const int k0 = c << 5;
            const uint32_t sb = sm + s * STAGE_BYTES;
            #pragma unroll
            for (int j = 0; j < 2; j++) {        // A hi(j=0) / lo(j=1)
                const __nv_bfloat16* src = (j == 0) ? Ahi : Alo;
                #pragma unroll
                for (int u = 0; u < 2; u++) {
                    int i   = u * 256 + tid;     // 0..511
                    int row = i >> 2, seg = i & 3;
                    cp16(sb + j * OFF_AL + row * A_STRIDE + seg * 16,
                         src + (size_t)(bm + row) * K + k0 + seg * 8);
                }
            }
            #pragma unroll
            for (int j = 0; j < 2; j++) {        // B hi / lo
                const __nv_bfloat16* src = (j == 0) ? Whi : Wlo;
                #pragma unroll
                for (int u = 0; u < 2; u++) {
                    int i = u * 256 + tid;
                    int kr = i >> 4, seg = i & 15;
                    cp16(sb + OFF_BH + j * SZ_B + kr * B_STRIDE + seg * 16,
                         src + (size_t)(k0 + kr) * N + bn + seg * 8);
                }
            }
        }
        CP_COMMIT();
    };

    load_stage(0);
    load_stage(1);

    const int lr = lane & 15;
    const int lc = lane >> 4;

    for (int c = 0; c < nch; c++) {
        load_stage(c + 2);
        CP_WAIT2();
        __syncthreads();

        const int s = c - (c / 3) * 3;
        const uint32_t sb = sm + s * STAGE_BYTES;

        #pragma unroll
        for (int ks = 0; ks < 2; ks++) {
            uint32_t ah[4][4], al[4][4], bh[2][4], bl[2][4];
            #pragma unroll
            for (int mf = 0; mf < 4; mf++) {
                uint32_t ao = sb + (wm * 64 + mf * 16 + lr) * A_STRIDE
                            + lc * 16 + ks * 32;
                ldsm4(ah[mf], ao);
                ldsm4(al[mf], ao + OFF_AL);
            }
            #pragma unroll
            for (int nt = 0; nt < 2; nt++) {
                uint32_t bo = sb + OFF_BH + (ks * 16 + lr) * B_STRIDE
                            + (wn * 32 + nt * 16 + lc * 8) * 2;
                ldsm4t(bh[nt], bo);
                ldsm4t(bl[nt], bo + SZ_B);
            }
            #pragma unroll
            for (int mf = 0; mf < 4; mf++)
                #pragma unroll
                for (int nf = 0; nf < 4; nf++) {
                    int nt = nf >> 1, p = (nf & 1) * 2;
                    mma_bf16(acc[mf][nf], ah[mf], bh[nt][p], bh[nt][p + 1]);
                    mma_bf16(acc[mf][nf], ah[mf], bl[nt][p], bl[nt][p + 1]);
                    mma_bf16(acc[mf][nf], al[mf], bh[nt][p], bh[nt][p + 1]);
                }
        }
        __syncthreads();
    }

    // ---- epilogue ----
    #pragma unroll
    for (int mf = 0; mf < 4; mf++) {
        #pragma unroll
        for (int nf = 0; nf < 4; nf++) {
            int col = bn + wn * 32 + nf * 8 + (lane & 3) * 2;
            float2 bv = *(const float2*)(bias + col);
            #pragma unroll
            for (int half = 0; half < 2; half++) {
                int row = bm + wm * 64 + mf * 16 + (lane >> 2) + half * 8;
                float v0 = acc[mf][nf][half * 2 + 0] + bv.x;
                float v1 = acc[mf][nf][half * 2 + 1] + bv.y;
                if (EPI == 1) {
                    v0 = gelu_f(v0); v1 = gelu_f(v1);
                    *(uint32_t*)(out_hi + (size_t)row * N + col) = pack_hi(v0, v1);
                    *(uint32_t*)(out_lo + (size_t)row * N + col) = pack_lo(v0, v1);
                } else {
                    if (EPI == 2) {
                        float2 rv = *(const float2*)(res + (size_t)row * N + col);
                        v0 += rv.x; v1 += rv.y;
                    }
                    *(float2*)(outf + (size_t)row * N + col) = make_float2(v0, v1);
                }
            }
        }
    }
}

// ---------------- LayerNorm -> bf16 hi/lo output --------------------------
__global__ __launch_bounds__(256) void ln_kernel(const float* __restrict__ x,
                                                 const float* __restrict__ w,
                                                 const float* __restrict__ b,
                                                 __nv_bfloat16* __restrict__ ohi,
                                                 __nv_bfloat16* __restrict__ olo)
{
    int row = blockIdx.x;
    int t   = threadIdx.x;
    const float4* xr = (const float4*)(x + (size_t)row * Cx);
    float4 v = xr[t];
    float s  = v.x + v.y + v.z + v.w;
    float sq = v.x*v.x + v.y*v.y + v.z*v.z + v.w*v.w;
    #pragma unroll
    for (int o = 16; o > 0; o >>= 1) {
        s  += __shfl_xor_sync(0xffffffffu, s,  o);
        sq += __shfl_xor_sync(0xffffffffu, sq, o);
    }
    __shared__ float ss[8], ssq[8];
    int wid = t >> 5, lane = t & 31;
    if (lane == 0) { ss[wid] = s; ssq[wid] = sq; }
    __syncthreads();
    float tot = 0.f, totq = 0.f;
    #pragma unroll
    for (int i = 0; i < 8; i++) { tot += ss[i]; totq += ssq[i]; }
    float mean = tot * (1.0f / Cx);
    float var  = totq * (1.0f / Cx) - mean * mean;
    float rstd = rsqrtf(var + 1e-5f);
    const float4 wv = ((const float4*)w)[t];
    const float4 bv = ((const float4*)b)[t];
    float o0 = (v.x - mean) * rstd * wv.x + bv.x;
    float o1 = (v.y - mean) * rstd * wv.y + bv.y;
    float o2 = (v.z - mean) * rstd * wv.z + bv.z;
    float o3 = (v.w - mean) * rstd * wv.w + bv.w;
    size_t idx = (size_t)row * Cx + t * 4;
    *(uint2*)(ohi + idx) = make_uint2(pack_hi(o0, o1), pack_hi(o2, o3));
    *(uint2*)(olo + idx) = make_uint2(pack_lo(o0, o1), pack_lo(o2, o3));
}

// ---------------- Causal flash attention (SIMT) -> bf16 hi/lo -------------
__global__ __launch_bounds__(64) void attn_kernel(const float* __restrict__ qkv,
                                                  __nv_bfloat16* __restrict__ yhi,
                                                  __nv_bfloat16* __restrict__ ylo)
{
    __shared__ float Ks[64][68];
    __shared__ float Vs[64][68];
    int qt  = blockIdx.x;
    int bh  = blockIdx.y;
    int b   = bh >> 4;
    int h   = bh & 15;
    int tid = threadIdx.x;
    int qi  = qt * 64 + tid;

    size_t base = (size_t)b * Lx * 3072;
    const float4* qp = (const float4*)(qkv + base + (size_t)qi * 3072 + h * 64);
    float q[64];
    #pragma unroll
    for (int i = 0; i < 16; i++) {
        float4 t = qp[i];
        q[4*i]   = t.x * 0.125f;
        q[4*i+1] = t.y * 0.125f;
        q[4*i+2] = t.z * 0.125f;
        q[4*i+3] = t.w * 0.125f;
    }
    float acc[64];
    #pragma unroll
    for (int i = 0; i < 64; i++) acc[i] = 0.f;
    float mval = -1e30f, l = 0.f;

    int ktiles = qt + 1;
    for (int kt = 0; kt < ktiles; kt++) {
        int k0 = kt * 64;
        __syncthreads();
        {
            const float4* kp = (const float4*)(qkv + base + (size_t)(k0 + tid) * 3072 + Cx   + h * 64);
            const float4* vp = (const float4*)(qkv + base + (size_t)(k0 + tid) * 3072 + 2*Cx + h * 64);
            float4* kd = (float4*)&Ks[tid][0];
            float4* vd = (float4*)&Vs[tid][0];
            #pragma unroll
            for (int i = 0; i < 16; i++) { kd[i] = kp[i]; vd[i] = vp[i]; }
        }
        __syncthreads();

        #pragma unroll 1
        for (int j0 = 0; j0 < 64; j0 += 16) {
            if (k0 + j0 > qi) break;
            float sarr[16];
            #pragma unroll
            for (int jj = 0; jj < 16; jj++) {
                const float4* kr = (const float4*)&Ks[j0 + jj][0];
                float d0 = 0.f, d1 = 0.f, d2 = 0.f, d3 = 0.f;
                #pragma unroll
                for (int i = 0; i < 16; i++) {
                    float4 kv = kr[i];
                    d0 += q[4*i]   * kv.x;
                    d1 += q[4*i+1] * kv.y;
                    d2 += q[4*i+2] * kv.z;
                    d3 += q[4*i+3] * kv.w;
                }
                float dot = (d0 + d1) + (d2 + d3);
                sarr[jj] = (k0 + j0 + jj <= qi) ? dot : -1e30f;
            }
            float cmax = sarr[0];
            #pragma unroll
            for (int jj = 1; jj < 16; jj++) cmax = fmaxf(cmax, sarr[jj]);
            float mnew = fmaxf(mval, cmax);
            float corr = __expf(mval - mnew);
            mval = mnew;
            l *= corr;
            #pragma unroll
            for (int i = 0; i < 64; i++) acc[i] *= corr;
            #pragma unroll
            for (int jj = 0; jj < 16; jj++) {
                float p = __expf(sarr[jj] - mval);
                l += p;
                const float4* vr = (const float4*)&Vs[j0 + jj][0];
                #pragma unroll
                for (int i = 0; i < 16; i++) {
                    float4 vv = vr[i];
                    acc[4*i]   += p * vv.x;
                    acc[4*i+1] += p * vv.y;
                    acc[4*i+2] += p * vv.z;
                    acc[4*i+3] += p * vv.w;
                }
            }
        }
    }

    float inv = 1.0f / l;
    size_t orow = ((size_t)(b * Lx + qi)) * Cx + h * 64;
    #pragma unroll
    for (int i = 0; i < 16; i++) {
        float o0 = acc[4*i]   * inv;
        float o1 = acc[4*i+1] * inv;
        float o2 = acc[4*i+2] * inv;
        float o3 = acc[4*i+3] * inv;
        *(uint2*)(yhi + orow + i * 4) = make_uint2(pack_hi(o0, o1), pack_hi(o2, o3));
        *(uint2*)(ylo + orow + i * 4) = make_uint2(pack_lo(o0, o1), pack_lo(o2, o3));
    }
}

// ---------------- launcher ----------------
extern "C" void kernel_launch(void* const* d_in, const int* in_sizes, int n_in,
                              void* d_out, int out_size)
{
    const float* x      = (const float*)d_in[0];
    const float* ln1_w  = (const float*)d_in[1];
    const float* ln1_b  = (const float*)d_in[2];
    const float* w_attn = (const float*)d_in[3];
    const float* b_attn = (const float*)d_in[4];
    const float* w_proj = (const float*)d_in[5];
    const float* b_proj = (const float*)d_in[6];
    const float* ln2_w  = (const float*)d_in[7];
    const float* ln2_b  = (const float*)d_in[8];
    const float* w_fc   = (const float*)d_in[9];
    const float* b_fc   = (const float*)d_in[10];
    const float* w_fc2  = (const float*)d_in[11];
    const float* b_fc2  = (const float*)d_in[12];
    float* out = (float*)d_out;

    void *pqkv, *px1, *phh, *phl, *pyh, *pyl, *pfh, *pfl;
    void *pwah, *pwal, *pwph, *pwpl, *pwfh, *pwfl, *pw2h, *pw2l;
    cudaGetSymbolAddress(&pqkv, g_qkv);
    cudaGetSymbolAddress(&px1,  g_x1);
    cudaGetSymbolAddress(&phh,  g_h_hi);  cudaGetSymbolAddress(&phl, g_h_lo);
    cudaGetSymbolAddress(&pyh,  g_y_hi);  cudaGetSymbolAddress(&pyl, g_y_lo);
    cudaGetSymbolAddress(&pfh,  g_fc_hi); cudaGetSymbolAddress(&pfl, g_fc_lo);
    cudaGetSymbolAddress(&pwah, g_wa_hi); cudaGetSymbolAddress(&pwal, g_wa_lo);
    cudaGetSymbolAddress(&pwph, g_wp_hi); cudaGetSymbolAddress(&pwpl, g_wp_lo);
    cudaGetSymbolAddress(&pwfh, g_wf_hi); cudaGetSymbolAddress(&pwfl, g_wf_lo);
    cudaGetSymbolAddress(&pw2h, g_wf2_hi); cudaGetSymbolAddress(&pw2l, g_wf2_lo);

    float* qkv = (float*)pqkv;
    float* x1  = (float*)px1;
    __nv_bfloat16 *hh = (__nv_bfloat16*)phh, *hl = (__nv_bfloat16*)phl;
    __nv_bfloat16 *yh = (__nv_bfloat16*)pyh, *yl = (__nv_bfloat16*)pyl;
    __nv_bfloat16 *fh = (__nv_bfloat16*)pfh, *fl = (__nv_bfloat16*)pfl;
    __nv_bfloat16 *wah = (__nv_bfloat16*)pwah, *wal = (__nv_bfloat16*)pwal;
    __nv_bfloat16 *wph = (__nv_bfloat16*)pwph, *wpl = (__nv_bfloat16*)pwpl;
    __nv_bfloat16 *wfh = (__nv_bfloat16*)pwfh, *wfl = (__nv_bfloat16*)pwfl;
    __nv_bfloat16 *w2h = (__nv_bfloat16*)pw2h, *w2l = (__nv_bfloat16*)pw2l;

    static bool attr_done = false;
    if (!attr_done) {
        cudaFuncSetAttribute(mma_gemm<0>, cudaFuncAttributeMaxDynamicSharedMemorySize, GEMM_SMEM);
        cudaFuncSetAttribute(mma_gemm<1>, cudaFuncAttributeMaxDynamicSharedMemorySize, GEMM_SMEM);
        cudaFuncSetAttribute(mma_gemm<2>, cudaFuncAttributeMaxDynamicSharedMemorySize, GEMM_SMEM);
        attr_done = true;
    }

    // 0) weight pre-conversion (fp32 -> bf16 hi/lo), per launch
    conv_w<<<(Cx*3*Cx/4 + 255)/256, 256>>>(w_attn, wah, wal, Cx*3*Cx/4);
    conv_w<<<(Cx*Cx/4   + 255)/256, 256>>>(w_proj, wph, wpl, Cx*Cx/4);
    conv_w<<<(Cx*4*Cx/4 + 255)/256, 256>>>(w_fc,   wfh, wfl, Cx*4*Cx/4);
    conv_w<<<(4*Cx*Cx/4 + 255)/256, 256>>>(w_fc2,  w2h, w2l, 4*Cx*Cx/4);

    // 1) h = LN1(x) -> bf16 hi/lo
    ln_kernel<<<Mrows, 256>>>(x, ln1_w, ln1_b, hh, hl);
    // 2) qkv = h @ w_attn + b_attn (fp32 out)
    mma_gemm<0><<<dim3(3*Cx/128, Mrows/128), 256, GEMM_SMEM>>>(
        hh, hl, wah, wal, b_attn, nullptr, qkv, nullptr, nullptr,
        Mrows, 3*Cx, Cx);
    // 3) y = causal_attention(qkv) -> bf16 hi/lo
    attn_kernel<<<dim3(Lx/64, Bsz*Hx), 64>>>(qkv, yh, yl);
    // 4) x1 = x + y @ w_proj + b_proj (fp32 out)
    mma_gemm<2><<<dim3(Cx/128, Mrows/128), 256, GEMM_SMEM>>>(
        yh, yl, wph, wpl, b_proj, x, x1, nullptr, nullptr,
        Mrows, Cx, Cx);
    // 5) h = LN2(x1) -> bf16 hi/lo
    ln_kernel<<<Mrows, 256>>>(x1, ln2_w, ln2_b, hh, hl);
    // 6) fc = gelu(h @ w_fc + b_fc) -> bf16 hi/lo only
    mma_gemm<1><<<dim3(4*Cx/128, Mrows/128), 256, GEMM_SMEM>>>(
        hh, hl, wfh, wfl, b_fc, nullptr, nullptr, fh, fl,
        Mrows, 4*Cx, Cx);
    // 7) out = x1 + fc @ w_fc2 + b_fc2 (fp32 out)
    mma_gemm<2><<<dim3(Cx/128, Mrows/128), 256, GEMM_SMEM>>>(
        fh, fl, w2h, w2l, b_fc2, x1, out, nullptr, nullptr,
        Mrows, Cx, 4*Cx);
}

// round 5
// speedup vs baseline: 3.2330x; 1.7448x over previous
#include <cuda_runtime.h>
#include <cuda_bf16.h>
#include <math.h>
#include <stdint.h>

// Problem constants
#define Bsz 2
#define Lx  2048
#define Cx  1024
#define Hx  16
#define Dx  64
#define Mrows (Bsz*Lx)      // 4096

// ---------------- scratch (__device__ globals: alloc-free) ----------------
__device__ float g_x1 [Mrows * Cx];

__device__ __nv_bfloat16 g_h_hi [Mrows * Cx];
__device__ __nv_bfloat16 g_h_lo [Mrows * Cx];
__device__ __nv_bfloat16 g_y_hi [Mrows * Cx];
__device__ __nv_bfloat16 g_y_lo [Mrows * Cx];
__device__ __nv_bfloat16 g_fc_hi[Mrows * 4 * Cx];
__device__ __nv_bfloat16 g_fc_lo[Mrows * 4 * Cx];

// attention operands, [B,H,L,D]
__device__ __nv_bfloat16 g_q_hi[Mrows * Cx];
__device__ __nv_bfloat16 g_q_lo[Mrows * Cx];
__device__ __nv_bfloat16 g_k_hi[Mrows * Cx];
__device__ __nv_bfloat16 g_k_lo[Mrows * Cx];
__device__ __nv_bfloat16 g_v_hi[Mrows * Cx];
__device__ __nv_bfloat16 g_v_lo[Mrows * Cx];

__device__ __nv_bfloat16 g_wa_hi [Cx * 3 * Cx];
__device__ __nv_bfloat16 g_wa_lo [Cx * 3 * Cx];
__device__ __nv_bfloat16 g_wp_hi [Cx * Cx];
__device__ __nv_bfloat16 g_wp_lo [Cx * Cx];
__device__ __nv_bfloat16 g_wf_hi [Cx * 4 * Cx];
__device__ __nv_bfloat16 g_wf_lo [Cx * 4 * Cx];
__device__ __nv_bfloat16 g_wf2_hi[4 * Cx * Cx];
__device__ __nv_bfloat16 g_wf2_lo[4 * Cx * Cx];

// ================= helpers ==========================
__device__ __forceinline__ uint32_t smem_u32(const void* p) {
    uint32_t a;
    asm("{ .reg .u64 t; cvta.to.shared.u64 t, %1; cvt.u32.u64 %0, t; }"
        : "=r"(a) : "l"(p));
    return a;
}
__device__ __forceinline__ float hi_part(float x) {
    return __uint_as_float(__float_as_uint(x) & 0xFFFF0000u);
}
__device__ __forceinline__ uint32_t pack_hi(float a, float b) {
    return __byte_perm(__float_as_uint(a), __float_as_uint(b), 0x7632);
}
__device__ __forceinline__ uint32_t pack_lo(float a, float b) {
    __nv_bfloat162 p = __floats2bfloat162_rn(a - hi_part(a), b - hi_part(b));
    return *(uint32_t*)&p;
}

__device__ __forceinline__ void cp16(uint32_t dst, const void* src) {
    asm volatile("cp.async.cg.shared.global [%0], [%1], 16;"
                 :: "r"(dst), "l"(src));
}
#define CP_COMMIT() asm volatile("cp.async.commit_group;" ::: "memory")
#define CP_WAIT0()  asm volatile("cp.async.wait_group 0;" ::: "memory")
#define CP_WAIT1()  asm volatile("cp.async.wait_group 1;" ::: "memory")
#define CP_WAIT2()  asm volatile("cp.async.wait_group 2;" ::: "memory")

__device__ __forceinline__ void ldsm4(uint32_t (&r)[4], uint32_t addr) {
    asm volatile("ldmatrix.sync.aligned.m8n8.x4.shared.b16 {%0,%1,%2,%3}, [%4];"
                 : "=r"(r[0]), "=r"(r[1]), "=r"(r[2]), "=r"(r[3]) : "r"(addr));
}
__device__ __forceinline__ void ldsm4t(uint32_t (&r)[4], uint32_t addr) {
    asm volatile("ldmatrix.sync.aligned.m8n8.x4.trans.shared.b16 {%0,%1,%2,%3}, [%4];"
                 : "=r"(r[0]), "=r"(r[1]), "=r"(r[2]), "=r"(r[3]) : "r"(addr));
}
__device__ __forceinline__ void mma_bf16(float (&c)[4], const uint32_t (&a)[4],
                                         uint32_t b0, uint32_t b1) {
    asm volatile(
        "mma.sync.aligned.m16n8k16.row.col.f32.bf16.bf16.f32 "
        "{%0,%1,%2,%3},{%4,%5,%6,%7},{%8,%9},{%0,%1,%2,%3};"
        : "+f"(c[0]), "+f"(c[1]), "+f"(c[2]), "+f"(c[3])
        : "r"(a[0]), "r"(a[1]), "r"(a[2]), "r"(a[3]), "r"(b0), "r"(b1));
}

__device__ __forceinline__ float gelu_f(float x) {
    float x3 = x * x * x;
    float t  = tanhf(0.7978845608028654f * (x + 0.044715f * x3));
    return 0.5f * x * (1.0f + t);
}

// exp2 on the FMA pipe (no MUFU): t <= 0 expected, deg-5 Taylor on [-0.5,0.5]
__device__ __forceinline__ float pexp2(float t) {
    t = fmaxf(t, -126.f);
    float k  = t + 12582912.f;                 // round-to-nearest int
    int   i  = __float_as_int(k) - 0x4B400000;
    float fi = k - 12582912.f;
    float f  = t - fi;                         // [-0.5, 0.5]
    float p  = 1.3333558e-3f;
    p = fmaf(p, f, 9.6181291e-3f);
    p = fmaf(p, f, 5.5504109e-2f);
    p = fmaf(p, f, 2.4022651e-1f);
    p = fmaf(p, f, 6.9314718e-1f);
    p = fmaf(p, f, 1.0f);
    return __int_as_float(__float_as_int(p) + (i << 23));
}
#define LOG2E 1.4426950408889634f

// ---------------- weight fp32 -> bf16 hi/lo (per-launch pre-pass) ---------
__global__ __launch_bounds__(256) void conv_w(const float* __restrict__ w,
                                              __nv_bfloat16* __restrict__ hi,
                                              __nv_bfloat16* __restrict__ lo,
                                              int n4)
{
    int i = blockIdx.x * 256 + threadIdx.x;
    if (i >= n4) return;
    float4 v = ((const float4*)w)[i];
    ((uint2*)hi)[i] = make_uint2(pack_hi(v.x, v.y), pack_hi(v.z, v.w));
    ((uint2*)lo)[i] = make_uint2(pack_lo(v.x, v.y), pack_lo(v.z, v.w));
}

// =========================================================================
// split-bf16 GEMM via mma.sync (as R3, passing) + new EPI=3 epilogue:
// EPI: 0 = bias -> fp32 out
//      1 = bias+gelu -> bf16 hi/lo out
//      2 = bias+residual -> fp32 out
//      3 = bias, split into Q(x0.125)/K/V hi/lo arrays in [B,H,L,D]
// =========================================================================
#define BKC 32
#define A_STRIDE 80
#define B_STRIDE 272
#define SZ_A (128 * A_STRIDE)
#define SZ_B (BKC * B_STRIDE)
#define OFF_AL SZ_A
#define OFF_BH (2 * SZ_A)
#define OFF_BL (2 * SZ_A + SZ_B)
#define STAGE_BYTES (2 * SZ_A + 2 * SZ_B)
#define GEMM_SMEM (3 * STAGE_BYTES)

template<int EPI>
__global__ __launch_bounds__(256) void mma_gemm(
    const __nv_bfloat16* __restrict__ Ahi, const __nv_bfloat16* __restrict__ Alo,
    const __nv_bfloat16* __restrict__ Whi, const __nv_bfloat16* __restrict__ Wlo,
    const float* __restrict__ bias, const float* __restrict__ res,
    float* __restrict__ outf,
    __nv_bfloat16* __restrict__ out_hi, __nv_bfloat16* __restrict__ out_lo,
    __nv_bfloat16* __restrict__ kh_, __nv_bfloat16* __restrict__ kl_,
    __nv_bfloat16* __restrict__ vh_, __nv_bfloat16* __restrict__ vl_,
    int M, int N, int K)
{
    extern __shared__ char smem_raw[];
    const uint32_t sm = smem_u32(smem_raw);

    const int tid  = threadIdx.x;
    const int wid  = tid >> 5;
    const int lane = tid & 31;
    const int bm   = blockIdx.y * 128;
    const int bn   = blockIdx.x * 128;
    const int wm   = wid >> 2;
    const int wn   = wid & 3;
    const int nch  = K >> 5;

    float acc[4][4][4];
    #pragma unroll
    for (int i = 0; i < 4; i++)
        #pragma unroll
        for (int j = 0; j < 4; j++)
            #pragma unroll
            for (int q = 0; q < 4; q++) acc[i][j][q] = 0.f;

    auto load_stage = [&](int c) {
        if (c < nch) {
            const int s  = c - (c / 3) * 3;
            const int k0 = c << 5;
            const uint32_t sb = sm + s * STAGE_BYTES;
            #pragma unroll
            for (int j = 0; j < 2; j++) {
                const __nv_bfloat16* src = (j == 0) ? Ahi : Alo;
                #pragma unroll
                for (int u = 0; u < 2; u++) {
                    int i   = u * 256 + tid;
                    int row = i >> 2, seg = i & 3;
                    cp16(sb + j * OFF_AL + row * A_STRIDE + seg * 16,
                         src + (size_t)(bm + row) * K + k0 + seg * 8);
                }
            }
            #pragma unroll
            for (int j = 0; j < 2; j++) {
                const __nv_bfloat16* src = (j == 0) ? Whi : Wlo;
                #pragma unroll
                for (int u = 0; u < 2; u++) {
                    int i = u * 256 + tid;
                    int kr = i >> 4, seg = i & 15;
                    cp16(sb + OFF_BH + j * SZ_B + kr * B_STRIDE + seg * 16,
                         src + (size_t)(k0 + kr) * N + bn + seg * 8);
                }
            }
        }
        CP_COMMIT();
    };

    load_stage(0);
    load_stage(1);

    const int lr = lane & 15;
    const int lc = lane >> 4;

    for (int c = 0; c < nch; c++) {
        load_stage(c + 2);
        CP_WAIT2();
        __syncthreads();

        const int s = c - (c / 3) * 3;
        const uint32_t sb = sm + s * STAGE_BYTES;

        #pragma unroll
        for (int ks = 0; ks < 2; ks++) {
            uint32_t ah[4][4], al[4][4], bh[2][4], bl[2][4];
            #pragma unroll
            for (int mf = 0; mf < 4; mf++) {
                uint32_t ao = sb + (wm * 64 + mf * 16 + lr) * A_STRIDE
                            + lc * 16 + ks * 32;
                ldsm4(ah[mf], ao);
                ldsm4(al[mf], ao + OFF_AL);
            }
            #pragma unroll
            for (int nt = 0; nt < 2; nt++) {
                uint32_t bo = sb + OFF_BH + (ks * 16 + lr) * B_STRIDE
                            + (wn * 32 + nt * 16 + lc * 8) * 2;
                ldsm4t(bh[nt], bo);
                ldsm4t(bl[nt], bo + SZ_B);
            }
            #pragma unroll
            for (int mf = 0; mf < 4; mf++)
                #pragma unroll
                for (int nf = 0; nf < 4; nf++) {
                    int nt = nf >> 1, p = (nf & 1) * 2;
                    mma_bf16(acc[mf][nf], ah[mf], bh[nt][p], bh[nt][p + 1]);
                    mma_bf16(acc[mf][nf], ah[mf], bl[nt][p], bl[nt][p + 1]);
                    mma_bf16(acc[mf][nf], al[mf], bh[nt][p], bh[nt][p + 1]);
                }
        }
        __syncthreads();
    }

    // ---- epilogue ----
    #pragma unroll
    for (int mf = 0; mf < 4; mf++) {
        #pragma unroll
        for (int nf = 0; nf < 4; nf++) {
            int col = bn + wn * 32 + nf * 8 + (lane & 3) * 2;
            float2 bv = *(const float2*)(bias + col);
            #pragma unroll
            for (int half = 0; half < 2; half++) {
                int row = bm + wm * 64 + mf * 16 + (lane >> 2) + half * 8;
                float v0 = acc[mf][nf][half * 2 + 0] + bv.x;
                float v1 = acc[mf][nf][half * 2 + 1] + bv.y;
                if (EPI == 1) {
                    v0 = gelu_f(v0); v1 = gelu_f(v1);
                    *(uint32_t*)(out_hi + (size_t)row * N + col) = pack_hi(v0, v1);
                    *(uint32_t*)(out_lo + (size_t)row * N + col) = pack_lo(v0, v1);
                } else if (EPI == 3) {
                    int sector = col >> 10;
                    int wcol = col & 1023;
                    int hh = wcol >> 6;
                    int dd = wcol & 63;
                    int brow = row >> 11;
                    int lrow = row & 2047;
                    size_t dst = ((size_t)(brow * Hx + hh) * Lx + lrow) * Dx + dd;
                    if (sector == 0) { v0 *= 0.125f; v1 *= 0.125f; }
                    __nv_bfloat16* Hd = (sector == 0) ? out_hi : (sector == 1) ? kh_ : vh_;
                    __nv_bfloat16* Ld = (sector == 0) ? out_lo : (sector == 1) ? kl_ : vl_;
                    *(uint32_t*)(Hd + dst) = pack_hi(v0, v1);
                    *(uint32_t*)(Ld + dst) = pack_lo(v0, v1);
                } else {
                    if (EPI == 2) {
                        float2 rv = *(const float2*)(res + (size_t)row * N + col);
                        v0 += rv.x; v1 += rv.y;
                    }
                    *(float2*)(outf + (size_t)row * N + col) = make_float2(v0, v1);
                }
            }
        }
    }
}

// ---------------- LayerNorm -> bf16 hi/lo output --------------------------
__global__ __launch_bounds__(256) void ln_kernel(const float* __restrict__ x,
                                                 const float* __restrict__ w,
                                                 const float* __restrict__ b,
                                                 __nv_bfloat16* __restrict__ ohi,
                                                 __nv_bfloat16* __restrict__ olo)
{
    int row = blockIdx.x;
    int t   = threadIdx.x;
    const float4* xr = (const float4*)(x + (size_t)row * Cx);
    float4 v = xr[t];
    float s  = v.x + v.y + v.z + v.w;
    float sq = v.x*v.x + v.y*v.y + v.z*v.z + v.w*v.w;
    #pragma unroll
    for (int o = 16; o > 0; o >>= 1) {
        s  += __shfl_xor_sync(0xffffffffu, s,  o);
        sq += __shfl_xor_sync(0xffffffffu, sq, o);
    }
    __shared__ float ss[8], ssq[8];
    int wid = t >> 5, lane = t & 31;
    if (lane == 0) { ss[wid] = s; ssq[wid] = sq; }
    __syncthreads();
    float tot = 0.f, totq = 0.f;
    #pragma unroll
    for (int i = 0; i < 8; i++) { tot += ss[i]; totq += ssq[i]; }
    float mean = tot * (1.0f / Cx);
    float var  = totq * (1.0f / Cx) - mean * mean;
    float rstd = rsqrtf(var + 1e-5f);
    const float4 wv = ((const float4*)w)[t];
    const float4 bv = ((const float4*)b)[t];
    float o0 = (v.x - mean) * rstd * wv.x + bv.x;
    float o1 = (v.y - mean) * rstd * wv.y + bv.y;
    float o2 = (v.z - mean) * rstd * wv.z + bv.z;
    float o3 = (v.w - mean) * rstd * wv.w + bv.w;
    size_t idx = (size_t)row * Cx + t * 4;
    *(uint2*)(ohi + idx) = make_uint2(pack_hi(o0, o1), pack_hi(o2, o3));
    *(uint2*)(olo + idx) = make_uint2(pack_lo(o0, o1), pack_lo(o2, o3));
}

// =========================================================================
// Tensor-core causal flash attention.
// grid (Lx/128, Bsz*Hx), 256 threads (8 warps, 16 q-rows per warp).
// Inputs: Q/K/V bf16 hi/lo in [B,H,L,D]; output y hi/lo in [B,L,C].
// smem: Qhi(128x144B) Qlo | double-buffered {Khi,Klo,Vhi,Vlo} 64x144B each.
// =========================================================================
#define QSTR 144
#define ATT_QS   18432            // 128*144
#define ATT_KV0  (2*ATT_QS)       // 36864
#define ATT_KVS  9216             // 64*144
#define ATT_STG  (4*ATT_KVS)      // 36864
#define ATT_SMEM (ATT_KV0 + 2*ATT_STG)  // 110592

__global__ __launch_bounds__(256, 1) void attn_mma(
    const __nv_bfloat16* __restrict__ qh, const __nv_bfloat16* __restrict__ ql,
    const __nv_bfloat16* __restrict__ kh, const __nv_bfloat16* __restrict__ kl,
    const __nv_bfloat16* __restrict__ vh, const __nv_bfloat16* __restrict__ vl,
    __nv_bfloat16* __restrict__ yh, __nv_bfloat16* __restrict__ yl)
{
    extern __shared__ char sm_raw[];
    const uint32_t S = smem_u32(sm_raw);
    const int tid = threadIdx.x, wid = tid >> 5, lane = tid & 31;
    const int qt  = gridDim.x - 1 - blockIdx.x;   // heavy CTAs first
    const int qb  = qt * 128;
    const int bh  = blockIdx.y;
    const size_t hb = (size_t)bh * Lx * Dx;

    const __nv_bfloat16 *Qh = qh + hb, *Ql = ql + hb;
    const __nv_bfloat16 *Kh = kh + hb, *Kl = kl + hb;
    const __nv_bfloat16 *Vh = vh + hb, *Vl = vl + hb;

    auto load_kv = [&](int kt, int s) {
        const uint32_t db = S + ATT_KV0 + s * ATT_STG;
        #pragma unroll
        for (int u = 0; u < 8; u++) {
            int j = u * 256 + tid;
            int arr = j >> 9;
            int rem = j & 511;
            int row = rem >> 3, seg = rem & 7;
            const __nv_bfloat16* src = (arr == 0) ? Kh : (arr == 1) ? Kl
                                     : (arr == 2) ? Vh : Vl;
            cp16(db + arr * ATT_KVS + row * QSTR + seg * 16,
                 src + (size_t)(kt * 64 + row) * Dx + seg * 8);
        }
    };

    // Q + KV0
    #pragma unroll
    for (int u = 0; u < 8; u++) {
        int j = u * 256 + tid;
        int arr = j >> 10;
        int rem = j & 1023;
        int row = rem >> 3, seg = rem & 7;
        const __nv_bfloat16* src = arr ? Ql : Qh;
        cp16(S + arr * ATT_QS + row * QSTR + seg * 16,
             src + (size_t)(qb + row) * Dx + seg * 8);
    }
    load_kv(0, 0);
    CP_COMMIT();
    CP_WAIT0();
    __syncthreads();

    // Q fragments (a-frags, 4 k-steps)
    uint32_t qhf[4][4], qlf[4][4];
    #pragma unroll
    for (int ks = 0; ks < 4; ks++) {
        uint32_t ao = S + (wid * 16 + (lane & 15)) * QSTR + (lane >> 4) * 16 + ks * 32;
        ldsm4(qhf[ks], ao);
        ldsm4(qlf[ks], ao + ATT_QS);
    }

    float oc[8][4];
    #pragma unroll
    for (int d = 0; d < 8; d++)
        #pragma unroll
        for (int i = 0; i < 4; i++) oc[d][i] = 0.f;
    float m0 = -1e30f, m1 = -1e30f, l0 = 0.f, l1 = 0.f;

    const int nk = 2 * qt + 2;
    const int wrow_min = qb + wid * 16;
    const int r0g = wrow_min + (lane >> 2);

    for (int kt = 0; kt < nk; kt++) {
        const int s = kt & 1;
        if (kt + 1 < nk) load_kv(kt + 1, s ^ 1);
        CP_COMMIT();
        if (kt > 0) { CP_WAIT1(); }
        __syncthreads();

        const int k0 = kt * 64;
        if (k0 <= wrow_min + 15) {     // warp has at least one unmasked row
            const uint32_t kb = S + ATT_KV0 + s * ATT_STG;

            // ---- S = Q @ K^T (3-term split) ----
            float sc[8][4];
            #pragma unroll
            for (int nt = 0; nt < 8; nt++)
                #pragma unroll
                for (int i = 0; i < 4; i++) sc[nt][i] = 0.f;

            #pragma unroll
            for (int ks = 0; ks < 4; ks++) {
                uint32_t kh4[4][4], kl4[4][4];
                #pragma unroll
                for (int ntp = 0; ntp < 4; ntp++) {
                    uint32_t ad = kb
                        + (uint32_t)((ntp * 16 + (lane & 7) + ((lane >> 4) << 3)) * QSTR)
                        + ((lane >> 3) & 1) * 16 + ks * 32;
                    ldsm4(kh4[ntp], ad);
                    ldsm4(kl4[ntp], ad + ATT_KVS);
                }
                #pragma unroll
                for (int ntp = 0; ntp < 4; ntp++)
                    #pragma unroll
                    for (int hf = 0; hf < 2; hf++) {
                        int nt = ntp * 2 + hf, p = hf * 2;
                        mma_bf16(sc[nt], qhf[ks], kh4[ntp][p], kh4[ntp][p + 1]);
                        mma_bf16(sc[nt], qhf[ks], kl4[ntp][p], kl4[ntp][p + 1]);
                        mma_bf16(sc[nt], qlf[ks], kh4[ntp][p], kh4[ntp][p + 1]);
                    }
            }

            // ---- causal mask (only near-diagonal tiles) ----
            if (k0 + 63 > wrow_min) {
                #pragma unroll
                for (int nt = 0; nt < 8; nt++) {
                    int key = k0 + nt * 8 + (lane & 3) * 2;
                    if (key     > r0g)     sc[nt][0] = -1e30f;
                    if (key + 1 > r0g)     sc[nt][1] = -1e30f;
                    if (key     > r0g + 8) sc[nt][2] = -1e30f;
                    if (key + 1 > r0g + 8) sc[nt][3] = -1e30f;
                }
            }

            // ---- online softmax (base-2 domain, FMA-pipe exp2) ----
            float rm0 = -1e30f, rm1 = -1e30f;
            #pragma unroll
            for (int nt = 0; nt < 8; nt++) {
                rm0 = fmaxf(rm0, fmaxf(sc[nt][0], sc[nt][1]));
                rm1 = fmaxf(rm1, fmaxf(sc[nt][2], sc[nt][3]));
            }
            rm0 = fmaxf(rm0, __shfl_xor_sync(0xffffffffu, rm0, 1));
            rm0 = fmaxf(rm0, __shfl_xor_sync(0xffffffffu, rm0, 2));
            rm1 = fmaxf(rm1, __shfl_xor_sync(0xffffffffu, rm1, 1));
            rm1 = fmaxf(rm1, __shfl_xor_sync(0xffffffffu, rm1, 2));
            float mn0 = fmaxf(m0, rm0 * LOG2E);
            float mn1 = fmaxf(m1, rm1 * LOG2E);
            float sc0 = pexp2(m0 - mn0);
            float sc1 = pexp2(m1 - mn1);
            m0 = mn0; m1 = mn1;
            l0 *= sc0; l1 *= sc1;
            #pragma unroll
            for (int d = 0; d < 8; d++) {
                oc[d][0] *= sc0; oc[d][1] *= sc0;
                oc[d][2] *= sc1; oc[d][3] *= sc1;
            }

            uint32_t pah[4][4], pal[4][4];
            float la0 = 0.f, la1 = 0.f;
            #pragma unroll
            for (int nt = 0; nt < 8; nt++) {
                float p0 = pexp2(fmaf(sc[nt][0], LOG2E, -m0));
                float p1 = pexp2(fmaf(sc[nt][1], LOG2E, -m0));
                float p2 = pexp2(fmaf(sc[nt][2], LOG2E, -m1));
                float p3 = pexp2(fmaf(sc[nt][3], LOG2E, -m1));
                la0 += p0 + p1;
                la1 += p2 + p3;
                int ks2 = nt >> 1, idx = (nt & 1) * 2;
                pah[ks2][idx]     = pack_hi(p0, p1);
                pah[ks2][idx + 1] = pack_hi(p2, p3);
                pal[ks2][idx]     = pack_lo(p0, p1);
                pal[ks2][idx + 1] = pack_lo(p2, p3);
            }
            l0 += la0; l1 += la1;

            // ---- O += P @ V (3-term split) ----
            #pragma unroll
            for (int ks2 = 0; ks2 < 4; ks2++) {
                uint32_t vh4[4][4], vl4[4][4];
                #pragma unroll
                for (int dtp = 0; dtp < 4; dtp++) {
                    uint32_t ad = kb + 2 * ATT_KVS
                        + (uint32_t)((ks2 * 16 + (lane & 15)) * QSTR)
                        + (dtp * 16 + (lane >> 4) * 8) * 2;
                    ldsm4t(vh4[dtp], ad);
                    ldsm4t(vl4[dtp], ad + ATT_KVS);
                }
                #pragma unroll
                for (int dtp = 0; dtp < 4; dtp++)
                    #pragma unroll
                    for (int hf = 0; hf < 2; hf++) {
                        int dt = dtp * 2 + hf, p = hf * 2;
                        mma_bf16(oc[dt], pah[ks2], vh4[dtp][p], vh4[dtp][p + 1]);
                        mma_bf16(oc[dt], pal[ks2], vh4[dtp][p], vh4[dtp][p + 1]);
                        mma_bf16(oc[dt], pah[ks2], vl4[dtp][p], vl4[dtp][p + 1]);
                    }
            }
        }
        __syncthreads();
    }

    // ---- finalize ----
    l0 += __shfl_xor_sync(0xffffffffu, l0, 1);
    l0 += __shfl_xor_sync(0xffffffffu, l0, 2);
    l1 += __shfl_xor_sync(0xffffffffu, l1, 1);
    l1 += __shfl_xor_sync(0xffffffffu, l1, 2);
    float i0 = 1.f / l0, i1 = 1.f / l1;

    const int b  = bh >> 4;
    const int hh = bh & 15;
    const size_t row0 = (size_t)b * Lx + qb + wid * 16 + (lane >> 2);
    const int colb = hh * 64 + (lane & 3) * 2;
    #pragma unroll
    for (int dt = 0; dt < 8; dt++) {
        float a0 = oc[dt][0] * i0, a1 = oc[dt][1] * i0;
        float a2 = oc[dt][2] * i1, a3 = oc[dt][3] * i1;
        size_t e0 = row0 * Cx + colb + dt * 8;
        size_t e1 = (row0 + 8) * Cx + colb + dt * 8;
        *(uint32_t*)(yh + e0) = pack_hi(a0, a1);
        *(uint32_t*)(yl + e0) = pack_lo(a0, a1);
        *(uint32_t*)(yh + e1) = pack_hi(a2, a3);
        *(uint32_t*)(yl + e1) = pack_lo(a2, a3);
    }
}

// ---------------- launcher ----------------
extern "C" void kernel_launch(void* const* d_in, const int* in_sizes, int n_in,
                              void* d_out, int out_size)
{
    const float* x      = (const float*)d_in[0];
    const float* ln1_w  = (const float*)d_in[1];
    const float* ln1_b  = (const float*)d_in[2];
    const float* w_attn = (const float*)d_in[3];
    const float* b_attn = (const float*)d_in[4];
    const float* w_proj = (const float*)d_in[5];
    const float* b_proj = (const float*)d_in[6];
    const float* ln2_w  = (const float*)d_in[7];
    const float* ln2_b  = (const float*)d_in[8];
    const float* w_fc   = (const float*)d_in[9];
    const float* b_fc   = (const float*)d_in[10];
    const float* w_fc2  = (const float*)d_in[11];
    const float* b_fc2  = (const float*)d_in[12];
    float* out = (float*)d_out;

    void *px1, *phh, *phl, *pyh, *pyl, *pfh, *pfl;
    void *pqh, *pql, *pkh, *pkl, *pvh, *pvl;
    void *pwah, *pwal, *pwph, *pwpl, *pwfh, *pwfl, *pw2h, *pw2l;
    cudaGetSymbolAddress(&px1,  g_x1);
    cudaGetSymbolAddress(&phh,  g_h_hi);  cudaGetSymbolAddress(&phl, g_h_lo);
    cudaGetSymbolAddress(&pyh,  g_y_hi);  cudaGetSymbolAddress(&pyl, g_y_lo);
    cudaGetSymbolAddress(&pfh,  g_fc_hi); cudaGetSymbolAddress(&pfl, g_fc_lo);
    cudaGetSymbolAddress(&pqh,  g_q_hi);  cudaGetSymbolAddress(&pql, g_q_lo);
    cudaGetSymbolAddress(&pkh,  g_k_hi);  cudaGetSymbolAddress(&pkl, g_k_lo);
    cudaGetSymbolAddress(&pvh,  g_v_hi);  cudaGetSymbolAddress(&pvl, g_v_lo);
    cudaGetSymbolAddress(&pwah, g_wa_hi); cudaGetSymbolAddress(&pwal, g_wa_lo);
    cudaGetSymbolAddress(&pwph, g_wp_hi); cudaGetSymbolAddress(&pwpl, g_wp_lo);
    cudaGetSymbolAddress(&pwfh, g_wf_hi); cudaGetSymbolAddress(&pwfl, g_wf_lo);
    cudaGetSymbolAddress(&pw2h, g_wf2_hi); cudaGetSymbolAddress(&pw2l, g_wf2_lo);

    float* x1  = (float*)px1;
    __nv_bfloat16 *hh = (__nv_bfloat16*)phh, *hl = (__nv_bfloat16*)phl;
    __nv_bfloat16 *yh = (__nv_bfloat16*)pyh, *yl = (__nv_bfloat16*)pyl;
    __nv_bfloat16 *fh = (__nv_bfloat16*)pfh, *fl = (__nv_bfloat16*)pfl;
    __nv_bfloat16 *qh = (__nv_bfloat16*)pqh, *ql = (__nv_bfloat16*)pql;
    __nv_bfloat16 *kh = (__nv_bfloat16*)pkh, *kl = (__nv_bfloat16*)pkl;
    __nv_bfloat16 *vh = (__nv_bfloat16*)pvh, *vl = (__nv_bfloat16*)pvl;
    __nv_bfloat16 *wah = (__nv_bfloat16*)pwah, *wal = (__nv_bfloat16*)pwal;
    __nv_bfloat16 *wph = (__nv_bfloat16*)pwph, *wpl = (__nv_bfloat16*)pwpl;
    __nv_bfloat16 *wfh = (__nv_bfloat16*)pwfh, *wfl = (__nv_bfloat16*)pwfl;
    __nv_bfloat16 *w2h = (__nv_bfloat16*)pw2h, *w2l = (__nv_bfloat16*)pw2l;

    static bool attr_done = false;
    if (!attr_done) {
        cudaFuncSetAttribute(mma_gemm<0>, cudaFuncAttributeMaxDynamicSharedMemorySize, GEMM_SMEM);
        cudaFuncSetAttribute(mma_gemm<1>, cudaFuncAttributeMaxDynamicSharedMemorySize, GEMM_SMEM);
        cudaFuncSetAttribute(mma_gemm<2>, cudaFuncAttributeMaxDynamicSharedMemorySize, GEMM_SMEM);
        cudaFuncSetAttribute(mma_gemm<3>, cudaFuncAttributeMaxDynamicSharedMemorySize, GEMM_SMEM);
        cudaFuncSetAttribute(attn_mma,    cudaFuncAttributeMaxDynamicSharedMemorySize, ATT_SMEM);
        attr_done = true;
    }

    // 0) weight pre-conversion
    conv_w<<<(Cx*3*Cx/4 + 255)/256, 256>>>(w_attn, wah, wal, Cx*3*Cx/4);
    conv_w<<<(Cx*Cx/4   + 255)/256, 256>>>(w_proj, wph, wpl, Cx*Cx/4);
    conv_w<<<(Cx*4*Cx/4 + 255)/256, 256>>>(w_fc,   wfh, wfl, Cx*4*Cx/4);
    conv_w<<<(4*Cx*Cx/4 + 255)/256, 256>>>(w_fc2,  w2h, w2l, 4*Cx*Cx/4);

    // 1) h = LN1(x)
    ln_kernel<<<Mrows, 256>>>(x, ln1_w, ln1_b, hh, hl);
    // 2) QKV GEMM -> split q/k/v hi/lo, [B,H,L,D], q pre-scaled by 1/sqrt(D)
    mma_gemm<3><<<dim3(3*Cx/128, Mrows/128), 256, GEMM_SMEM>>>(
        hh, hl, wah, wal, b_attn, nullptr, nullptr, qh, ql, kh, kl, vh, vl,
        Mrows, 3*Cx, Cx);
    // 3) y = causal flash attention (tensor cores)
    attn_mma<<<dim3(Lx/128, Bsz*Hx), 256, ATT_SMEM>>>(
        qh, ql, kh, kl, vh, vl, yh, yl);
    // 4) x1 = x + y @ w_proj + b_proj
    mma_gemm<2><<<dim3(Cx/128, Mrows/128), 256, GEMM_SMEM>>>(
        yh, yl, wph, wpl, b_proj, x, x1, nullptr, nullptr,
        nullptr, nullptr, nullptr, nullptr, Mrows, Cx, Cx);
    // 5) h = LN2(x1)
    ln_kernel<<<Mrows, 256>>>(x1, ln2_w, ln2_b, hh, hl);
    // 6) fc = gelu(h @ w_fc + b_fc) -> bf16 hi/lo
    mma_gemm<1><<<dim3(4*Cx/128, Mrows/128), 256, GEMM_SMEM>>>(
        hh, hl, wfh, wfl, b_fc, nullptr, nullptr, fh, fl,
        nullptr, nullptr, nullptr, nullptr, Mrows, 4*Cx, Cx);
    // 7) out = x1 + fc @ w_fc2 + b_fc2
    mma_gemm<2><<<dim3(Cx/128, Mrows/128), 256, GEMM_SMEM>>>(
        fh, fl, w2h, w2l, b_fc2, x1, out, nullptr, nullptr,
        nullptr, nullptr, nullptr, nullptr, Mrows, Cx, 4*Cx);
}

// round 6
// speedup vs baseline: 4.1930x; 1.2969x over previous
#include <cuda_runtime.h>
#include <cuda_fp16.h>
#include <math.h>
#include <stdint.h>

// Problem constants
#define Bsz 2
#define Lx  2048
#define Cx  1024
#define Hx  16
#define Dx  64
#define Mrows (Bsz*Lx)      // 4096

// ---------------- scratch (__device__ globals: alloc-free) ----------------
__device__ float g_x1 [Mrows * Cx];

__device__ __half g_h  [Mrows * Cx];       // LN out (A operand)
__device__ __half g_y  [Mrows * Cx];       // attention out (A operand)
__device__ __half g_fc [Mrows * 4 * Cx];   // gelu out (A operand)

// attention operands, [B,H,L,D]
__device__ __half g_q  [Mrows * Cx];       // fp16 (A side)
__device__ __half g_kh [Mrows * Cx];
__device__ __half g_kls[Mrows * Cx];       // (k - kh) * 2048
__device__ __half g_vh [Mrows * Cx];
__device__ __half g_vls[Mrows * Cx];

// weights: hi + scaled lo
__device__ __half g_wa_h [Cx * 3 * Cx];
__device__ __half g_wa_l [Cx * 3 * Cx];
__device__ __half g_wp_h [Cx * Cx];
__device__ __half g_wp_l [Cx * Cx];
__device__ __half g_wf_h [Cx * 4 * Cx];
__device__ __half g_wf_l [Cx * 4 * Cx];
__device__ __half g_w2_h [4 * Cx * Cx];
__device__ __half g_w2_l [4 * Cx * Cx];

// ================= helpers ==========================
__device__ __forceinline__ uint32_t smem_u32(const void* p) {
    uint32_t a;
    asm("{ .reg .u64 t; cvta.to.shared.u64 t, %1; cvt.u32.u64 %0, t; }"
        : "=r"(a) : "l"(p));
    return a;
}
__device__ __forceinline__ uint32_t pack_h(float a, float b) {
    __half2 h = __floats2half2_rn(a, b);
    return *(uint32_t*)&h;
}
__device__ __forceinline__ uint32_t pack_ls(float a, float b) {
    float ha = __half2float(__float2half_rn(a));
    float hb = __half2float(__float2half_rn(b));
    __half2 h = __floats2half2_rn((a - ha) * 2048.f, (b - hb) * 2048.f);
    return *(uint32_t*)&h;
}
// multiply packed fp16x2 by 2^-11 (0x1000 = fp16 2^-11)
__device__ __forceinline__ uint32_t hscale(uint32_t x) {
    uint32_t r;
    asm("mul.rn.f16x2 %0, %1, %2;" : "=r"(r) : "r"(x), "r"(0x10001000u));
    return r;
}

__device__ __forceinline__ void cp16(uint32_t dst, const void* src) {
    asm volatile("cp.async.cg.shared.global [%0], [%1], 16;"
                 :: "r"(dst), "l"(src));
}
#define CP_COMMIT() asm volatile("cp.async.commit_group;" ::: "memory")
#define CP_WAIT1()  asm volatile("cp.async.wait_group 1;" ::: "memory")
#define CP_WAIT2()  asm volatile("cp.async.wait_group 2;" ::: "memory")

__device__ __forceinline__ void ldsm4(uint32_t (&r)[4], uint32_t addr) {
    asm volatile("ldmatrix.sync.aligned.m8n8.x4.shared.b16 {%0,%1,%2,%3}, [%4];"
                 : "=r"(r[0]), "=r"(r[1]), "=r"(r[2]), "=r"(r[3]) : "r"(addr));
}
__device__ __forceinline__ void ldsm4t(uint32_t (&r)[4], uint32_t addr) {
    asm volatile("ldmatrix.sync.aligned.m8n8.x4.trans.shared.b16 {%0,%1,%2,%3}, [%4];"
                 : "=r"(r[0]), "=r"(r[1]), "=r"(r[2]), "=r"(r[3]) : "r"(addr));
}
__device__ __forceinline__ void mma_f16(float (&c)[4], const uint32_t (&a)[4],
                                        uint32_t b0, uint32_t b1) {
    asm volatile(
        "mma.sync.aligned.m16n8k16.row.col.f32.f16.f16.f32 "
        "{%0,%1,%2,%3},{%4,%5,%6,%7},{%8,%9},{%0,%1,%2,%3};"
        : "+f"(c[0]), "+f"(c[1]), "+f"(c[2]), "+f"(c[3])
        : "r"(a[0]), "r"(a[1]), "r"(a[2]), "r"(a[3]), "r"(b0), "r"(b1));
}

__device__ __forceinline__ float gelu_f(float x) {
    float x3 = x * x * x;
    float t  = tanhf(0.7978845608028654f * (x + 0.044715f * x3));
    return 0.5f * x * (1.0f + t);
}

// exp2 on the FMA pipe
__device__ __forceinline__ float pexp2(float t) {
    t = fmaxf(t, -126.f);
    float k  = t + 12582912.f;
    int   i  = __float_as_int(k) - 0x4B400000;
    float fi = k - 12582912.f;
    float f  = t - fi;
    float p  = 1.3333558e-3f;
    p = fmaf(p, f, 9.6181291e-3f);
    p = fmaf(p, f, 5.5504109e-2f);
    p = fmaf(p, f, 2.4022651e-1f);
    p = fmaf(p, f, 6.9314718e-1f);
    p = fmaf(p, f, 1.0f);
    return __int_as_float(__float_as_int(p) + (i << 23));
}
#define LOG2E 1.4426950408889634f

// ---------------- weight fp32 -> fp16 hi + scaled lo ----------------------
__global__ __launch_bounds__(256) void conv_w(const float* __restrict__ w,
                                              __half* __restrict__ hi,
                                              __half* __restrict__ ls,
                                              int n4)
{
    int i = blockIdx.x * 256 + threadIdx.x;
    if (i >= n4) return;
    float4 v = ((const float4*)w)[i];
    ((uint2*)hi)[i] = make_uint2(pack_h(v.x, v.y),  pack_h(v.z, v.w));
    ((uint2*)ls)[i] = make_uint2(pack_ls(v.x, v.y), pack_ls(v.z, v.w));
}

// =========================================================================
// 2-term split-fp16 GEMM: out = A[M,K] @ W[K,N] + bias (+epilogue)
// A: single fp16 [M,K]; W: fp16 hi + scaled lo [K,N].
// acc = Ah*Wh + (Ah*2^-11)*(Wls)      (Wls = (W-Wh)*2^11)
// EPI: 1 = bias+gelu -> fp16 out
//      2 = bias+residual -> fp32 out
//      3 = bias, split into Q(x0.125 fp16)/K(h,ls)/V(h,ls) in [B,H,L,D]
// CTA 128x128, 8 warps (64x32 warp tile), BK=32, 4-stage single-sync pipe.
// =========================================================================
#define A_STRIDE 80
#define B_STRIDE 272
#define SZ_A (128 * A_STRIDE)          // 10240
#define SZ_B (32 * B_STRIDE)           // 8704
#define OFF_B  SZ_A                    // 10240
#define OFF_BL (SZ_A + SZ_B)           // 18944
#define STAGE_BYTES (SZ_A + 2 * SZ_B)  // 27648
#define GEMM_SMEM (4 * STAGE_BYTES)    // 110592

template<int EPI>
__global__ __launch_bounds__(256, 1) void mma_gemm(
    const __half* __restrict__ A,
    const __half* __restrict__ Wh, const __half* __restrict__ Wls,
    const float* __restrict__ bias, const float* __restrict__ res,
    float* __restrict__ outf, __half* __restrict__ outh,
    __half* __restrict__ q_, __half* __restrict__ kh_, __half* __restrict__ kls_,
    __half* __restrict__ vh_, __half* __restrict__ vls_,
    int M, int N, int K)
{
    extern __shared__ char smem_raw[];
    const uint32_t sm = smem_u32(smem_raw);

    const int tid  = threadIdx.x;
    const int wid  = tid >> 5;
    const int lane = tid & 31;
    const int bm   = blockIdx.y * 128;
    const int bn   = blockIdx.x * 128;
    const int wm   = wid >> 2;
    const int wn   = wid & 3;
    const int nch  = K >> 5;

    float acc[4][4][4];
    #pragma unroll
    for (int i = 0; i < 4; i++)
        #pragma unroll
        for (int j = 0; j < 4; j++)
            #pragma unroll
            for (int q = 0; q < 4; q++) acc[i][j][q] = 0.f;

    auto load_stage = [&](int c) {
        if (c < nch) {
            const int s  = c & 3;
            const int k0 = c << 5;
            const uint32_t sb = sm + s * STAGE_BYTES;
            // A: 128 rows x 32 k = 8KB -> 512 segs, 2/thread
            #pragma unroll
            for (int u = 0; u < 2; u++) {
                int f   = u * 256 + tid;
                int row = f >> 2, seg = f & 3;
                cp16(sb + row * A_STRIDE + seg * 16,
                     A + (size_t)(bm + row) * K + k0 + seg * 8);
            }
            // B hi + ls: 2 x (32 x 128) -> 1024 segs, 4/thread
            #pragma unroll
            for (int j = 0; j < 2; j++) {
                const __half* src = (j == 0) ? Wh : Wls;
                #pragma unroll
                for (int u = 0; u < 2; u++) {
                    int i  = u * 256 + tid;
                    int kr = i >> 4, seg = i & 15;
                    cp16(sb + OFF_B + j * SZ_B + kr * B_STRIDE + seg * 16,
                         src + (size_t)(k0 + kr) * N + bn + seg * 8);
                }
            }
        }
        CP_COMMIT();
    };

    load_stage(0);
    load_stage(1);
    load_stage(2);

    const int lr = lane & 15;
    const int lc = lane >> 4;

    for (int c = 0; c < nch; c++) {
        CP_WAIT2();
        __syncthreads();
        load_stage(c + 3);

        const uint32_t sb = sm + (c & 3) * STAGE_BYTES;

        #pragma unroll
        for (int ks = 0; ks < 2; ks++) {
            uint32_t ah[4][4], as[4][4], bh[2][4], bl[2][4];
            #pragma unroll
            for (int mf = 0; mf < 4; mf++) {
                uint32_t ao = sb + (wm * 64 + mf * 16 + lr) * A_STRIDE
                            + lc * 16 + ks * 32;
                ldsm4(ah[mf], ao);
                #pragma unroll
                for (int r = 0; r < 4; r++) as[mf][r] = hscale(ah[mf][r]);
            }
            #pragma unroll
            for (int nt = 0; nt < 2; nt++) {
                uint32_t bo = sb + OFF_B + (ks * 16 + lr) * B_STRIDE
                            + (wn * 32 + nt * 16 + lc * 8) * 2;
                ldsm4t(bh[nt], bo);
                ldsm4t(bl[nt], bo + SZ_B);
            }
            #pragma unroll
            for (int mf = 0; mf < 4; mf++)
                #pragma unroll
                for (int nf = 0; nf < 4; nf++) {
                    int nt = nf >> 1, p = (nf & 1) * 2;
                    mma_f16(acc[mf][nf], ah[mf], bh[nt][p], bh[nt][p + 1]);
                    mma_f16(acc[mf][nf], as[mf], bl[nt][p], bl[nt][p + 1]);
                }
        }
    }

    // ---- epilogue ----
    #pragma unroll
    for (int mf = 0; mf < 4; mf++) {
        #pragma unroll
        for (int nf = 0; nf < 4; nf++) {
            int col = bn + wn * 32 + nf * 8 + (lane & 3) * 2;
            float2 bv = *(const float2*)(bias + col);
            #pragma unroll
            for (int half = 0; half < 2; half++) {
                int row = bm + wm * 64 + mf * 16 + (lane >> 2) + half * 8;
                float v0 = acc[mf][nf][half * 2 + 0] + bv.x;
                float v1 = acc[mf][nf][half * 2 + 1] + bv.y;
                if (EPI == 1) {
                    v0 = gelu_f(v0); v1 = gelu_f(v1);
                    *(uint32_t*)(outh + (size_t)row * N + col) = pack_h(v0, v1);
                } else if (EPI == 3) {
                    int sector = col >> 10;
                    int wcol = col & 1023;
                    int hh = wcol >> 6;
                    int dd = wcol & 63;
                    int brow = row >> 11;
                    int lrow = row & 2047;
                    size_t dst = ((size_t)(brow * Hx + hh) * Lx + lrow) * Dx + dd;
                    if (sector == 0) {
                        *(uint32_t*)(q_ + dst) = pack_h(v0 * 0.125f, v1 * 0.125f);
                    } else if (sector == 1) {
                        *(uint32_t*)(kh_  + dst) = pack_h(v0, v1);
                        *(uint32_t*)(kls_ + dst) = pack_ls(v0, v1);
                    } else {
                        *(uint32_t*)(vh_  + dst) = pack_h(v0, v1);
                        *(uint32_t*)(vls_ + dst) = pack_ls(v0, v1);
                    }
                } else {
                    float2 rv = *(const float2*)(res + (size_t)row * N + col);
                    v0 += rv.x; v1 += rv.y;
                    *(float2*)(outf + (size_t)row * N + col) = make_float2(v0, v1);
                }
            }
        }
    }
}

// ---------------- LayerNorm -> fp16 output --------------------------------
__global__ __launch_bounds__(256) void ln_kernel(const float* __restrict__ x,
                                                 const float* __restrict__ w,
                                                 const float* __restrict__ b,
                                                 __half* __restrict__ oh)
{
    int row = blockIdx.x;
    int t   = threadIdx.x;
    const float4* xr = (const float4*)(x + (size_t)row * Cx);
    float4 v = xr[t];
    float s  = v.x + v.y + v.z + v.w;
    float sq = v.x*v.x + v.y*v.y + v.z*v.z + v.w*v.w;
    #pragma unroll
    for (int o = 16; o > 0; o >>= 1) {
        s  += __shfl_xor_sync(0xffffffffu, s,  o);
        sq += __shfl_xor_sync(0xffffffffu, sq, o);
    }
    __shared__ float ss[8], ssq[8];
    int wid = t >> 5, lane = t & 31;
    if (lane == 0) { ss[wid] = s; ssq[wid] = sq; }
    __syncthreads();
    float tot = 0.f, totq = 0.f;
    #pragma unroll
    for (int i = 0; i < 8; i++) { tot += ss[i]; totq += ssq[i]; }
    float mean = tot * (1.0f / Cx);
    float var  = totq * (1.0f / Cx) - mean * mean;
    float rstd = rsqrtf(var + 1e-5f);
    const float4 wv = ((const float4*)w)[t];
    const float4 bv = ((const float4*)b)[t];
    float o0 = (v.x - mean) * rstd * wv.x + bv.x;
    float o1 = (v.y - mean) * rstd * wv.y + bv.y;
    float o2 = (v.z - mean) * rstd * wv.z + bv.z;
    float o3 = (v.w - mean) * rstd * wv.w + bv.w;
    size_t idx = (size_t)row * Cx + t * 4;
    *(uint2*)(oh + idx) = make_uint2(pack_h(o0, o1), pack_h(o2, o3));
}

// =========================================================================
// Tensor-core causal flash attention, 2-term split-fp16.
// grid (Lx/128, Bsz*Hx), 256 threads.
// smem: Q(128x144B) | 3-stage {Kh,Kls,Vh,Vls} 64x144B each.
// =========================================================================
#define QSTR 144
#define ATT_QS   18432            // 128*144
#define ATT_KVS  9216             // 64*144
#define ATT_STG  (4*ATT_KVS)      // 36864
#define ATT_SMEM (ATT_QS + 3*ATT_STG)  // 129024

__global__ __launch_bounds__(256, 1) void attn_mma(
    const __half* __restrict__ q_,
    const __half* __restrict__ kh_, const __half* __restrict__ kls_,
    const __half* __restrict__ vh_, const __half* __restrict__ vls_,
    __half* __restrict__ y_)
{
    extern __shared__ char sm_raw[];
    const uint32_t S = smem_u32(sm_raw);
    const int tid = threadIdx.x, wid = tid >> 5, lane = tid & 31;
    const int qt  = gridDim.x - 1 - blockIdx.x;   // heavy CTAs first
    const int qb  = qt * 128;
    const int bh  = blockIdx.y;
    const size_t hb = (size_t)bh * Lx * Dx;

    const __half *Q  = q_  + hb;
    const __half *Kh = kh_ + hb, *Kl = kls_ + hb;
    const __half *Vh = vh_ + hb, *Vl = vls_ + hb;

    const int nk = 2 * qt + 2;

    auto load_kv = [&](int kt) {
        if (kt < nk) {
            const uint32_t db = S + ATT_QS + (kt % 3) * ATT_STG;
            #pragma unroll
            for (int u = 0; u < 8; u++) {
                int j = u * 256 + tid;
                int arr = j >> 9;
                int rem = j & 511;
                int row = rem >> 3, seg = rem & 7;
                const __half* src = (arr == 0) ? Kh : (arr == 1) ? Kl
                                   : (arr == 2) ? Vh : Vl;
                cp16(db + arr * ATT_KVS + row * QSTR + seg * 16,
                     src + (size_t)(kt * 64 + row) * Dx + seg * 8);
            }
        }
        CP_COMMIT();
    };

    // prologue: G0 = {Q, kv0}, G1 = {kv1}
    #pragma unroll
    for (int u = 0; u < 4; u++) {
        int j = u * 256 + tid;
        int row = j >> 3, seg = j & 7;
        cp16(S + row * QSTR + seg * 16,
             Q + (size_t)(qb + row) * Dx + seg * 8);
    }
    {   // kv0 into same group as Q
        const uint32_t db = S + ATT_QS;
        #pragma unroll
        for (int u = 0; u < 8; u++) {
            int j = u * 256 + tid;
            int arr = j >> 9;
            int rem = j & 511;
            int row = rem >> 3, seg = rem & 7;
            const __half* src = (arr == 0) ? Kh : (arr == 1) ? Kl
                               : (arr == 2) ? Vh : Vl;
            cp16(db + arr * ATT_KVS + row * QSTR + seg * 16,
                 src + (size_t)row * Dx + seg * 8);
        }
        CP_COMMIT();
    }
    load_kv(1);

    uint32_t qf[4][4], qs[4][4];
    float oc[8][4];
    #pragma unroll
    for (int d = 0; d < 8; d++)
        #pragma unroll
        for (int i = 0; i < 4; i++) oc[d][i] = 0.f;
    float m0 = -1e30f, m1 = -1e30f, l0 = 0.f, l1 = 0.f;

    const int wrow_min = qb + wid * 16;
    const int r0g = wrow_min + (lane >> 2);

    for (int kt = 0; kt < nk; kt++) {
        CP_WAIT1();
        __syncthreads();
        if (kt == 0) {
            #pragma unroll
            for (int ks = 0; ks < 4; ks++) {
                uint32_t ao = S + (wid * 16 + (lane & 15)) * QSTR
                            + (lane >> 4) * 16 + ks * 32;
                ldsm4(qf[ks], ao);
                #pragma unroll
                for (int r = 0; r < 4; r++) qs[ks][r] = hscale(qf[ks][r]);
            }
        }
        load_kv(kt + 2);

        const int k0 = kt * 64;
        if (k0 <= wrow_min + 15) {
            const uint32_t kb = S + ATT_QS + (kt % 3) * ATT_STG;

            // ---- S = Q @ K^T ----
            float sc[8][4];
            #pragma unroll
            for (int nt = 0; nt < 8; nt++)
                #pragma unroll
                for (int i = 0; i < 4; i++) sc[nt][i] = 0.f;

            #pragma unroll
            for (int ks = 0; ks < 4; ks++) {
                uint32_t k4[4][4], kl4[4][4];
                #pragma unroll
                for (int ntp = 0; ntp < 4; ntp++) {
                    uint32_t ad = kb
                        + (uint32_t)((ntp * 16 + (lane & 7) + ((lane >> 4) << 3)) * QSTR)
                        + ((lane >> 3) & 1) * 16 + ks * 32;
                    ldsm4(k4[ntp], ad);
                    ldsm4(kl4[ntp], ad + ATT_KVS);
                }
                #pragma unroll
                for (int ntp = 0; ntp < 4; ntp++)
                    #pragma unroll
                    for (int hf = 0; hf < 2; hf++) {
                        int nt = ntp * 2 + hf, p = hf * 2;
                        mma_f16(sc[nt], qf[ks], k4[ntp][p],  k4[ntp][p + 1]);
                        mma_f16(sc[nt], qs[ks], kl4[ntp][p], kl4[ntp][p + 1]);
                    }
            }

            // ---- causal mask ----
            if (k0 + 63 > wrow_min) {
                #pragma unroll
                for (int nt = 0; nt < 8; nt++) {
                    int key = k0 + nt * 8 + (lane & 3) * 2;
                    if (key     > r0g)     sc[nt][0] = -1e30f;
                    if (key + 1 > r0g)     sc[nt][1] = -1e30f;
                    if (key     > r0g + 8) sc[nt][2] = -1e30f;
                    if (key + 1 > r0g + 8) sc[nt][3] = -1e30f;
                }
            }

            // ---- online softmax (base-2, FMA exp2) ----
            float rm0 = -1e30f, rm1 = -1e30f;
            #pragma unroll
            for (int nt = 0; nt < 8; nt++) {
                rm0 = fmaxf(rm0, fmaxf(sc[nt][0], sc[nt][1]));
                rm1 = fmaxf(rm1, fmaxf(sc[nt][2], sc[nt][3]));
            }
            rm0 = fmaxf(rm0, __shfl_xor_sync(0xffffffffu, rm0, 1));
            rm0 = fmaxf(rm0, __shfl_xor_sync(0xffffffffu, rm0, 2));
            rm1 = fmaxf(rm1, __shfl_xor_sync(0xffffffffu, rm1, 1));
            rm1 = fmaxf(rm1, __shfl_xor_sync(0xffffffffu, rm1, 2));
            float mn0 = fmaxf(m0, rm0 * LOG2E);
            float mn1 = fmaxf(m1, rm1 * LOG2E);
            float s0 = pexp2(m0 - mn0);
            float s1 = pexp2(m1 - mn1);
            m0 = mn0; m1 = mn1;
            l0 *= s0; l1 *= s1;
            #pragma unroll
            for (int d = 0; d < 8; d++) {
                oc[d][0] *= s0; oc[d][1] *= s0;
                oc[d][2] *= s1; oc[d][3] *= s1;
            }

            uint32_t pa[4][4], pas[4][4];
            float la0 = 0.f, la1 = 0.f;
            #pragma unroll
            for (int nt = 0; nt < 8; nt++) {
                float p0 = pexp2(fmaf(sc[nt][0], LOG2E, -m0));
                float p1 = pexp2(fmaf(sc[nt][1], LOG2E, -m0));
                float p2 = pexp2(fmaf(sc[nt][2], LOG2E, -m1));
                float p3 = pexp2(fmaf(sc[nt][3], LOG2E, -m1));
                la0 += p0 + p1;
                la1 += p2 + p3;
                int ks2 = nt >> 1, idx = (nt & 1) * 2;
                pa[ks2][idx]     = pack_h(p0, p1);
                pa[ks2][idx + 1] = pack_h(p2, p3);
            }
            l0 += la0; l1 += la1;
            #pragma unroll
            for (int ks2 = 0; ks2 < 4; ks2++)
                #pragma unroll
                for (int r = 0; r < 4; r++) pas[ks2][r] = hscale(pa[ks2][r]);

            // ---- O += P @ V ----
            #pragma unroll
            for (int ks2 = 0; ks2 < 4; ks2++) {
                uint32_t v4[4][4], vl4[4][4];
                #pragma unroll
                for (int dtp = 0; dtp < 4; dtp++) {
                    uint32_t ad = kb + 2 * ATT_KVS
                        + (uint32_t)((ks2 * 16 + (lane & 15)) * QSTR)
                        + (dtp * 16 + (lane >> 4) * 8) * 2;
                    ldsm4t(v4[dtp], ad);
                    ldsm4t(vl4[dtp], ad + ATT_KVS);
                }
                #pragma unroll
                for (int dtp = 0; dtp < 4; dtp++)
                    #pragma unroll
                    for (int hf = 0; hf < 2; hf++) {
                        int dt = dtp * 2 + hf, p = hf * 2;
                        mma_f16(oc[dt], pa[ks2],  v4[dtp][p],  v4[dtp][p + 1]);
                        mma_f16(oc[dt], pas[ks2], vl4[dtp][p], vl4[dtp][p + 1]);
                    }
            }
        }
    }

    // ---- finalize ----
    l0 += __shfl_xor_sync(0xffffffffu, l0, 1);
    l0 += __shfl_xor_sync(0xffffffffu, l0, 2);
    l1 += __shfl_xor_sync(0xffffffffu, l1, 1);
    l1 += __shfl_xor_sync(0xffffffffu, l1, 2);
    float i0 = 1.f / l0, i1 = 1.f / l1;

    const int b  = bh >> 4;
    const int hh = bh & 15;
    const size_t row0 = (size_t)b * Lx + qb + wid * 16 + (lane >> 2);
    const int colb = hh * 64 + (lane & 3) * 2;
    #pragma unroll
    for (int dt = 0; dt < 8; dt++) {
        float a0 = oc[dt][0] * i0, a1 = oc[dt][1] * i0;
        float a2 = oc[dt][2] * i1, a3 = oc[dt][3] * i1;
        *(uint32_t*)(y_ + row0 * Cx + colb + dt * 8)       = pack_h(a0, a1);
        *(uint32_t*)(y_ + (row0 + 8) * Cx + colb + dt * 8) = pack_h(a2, a3);
    }
}

// ---------------- launcher ----------------
extern "C" void kernel_launch(void* const* d_in, const int* in_sizes, int n_in,
                              void* d_out, int out_size)
{
    const float* x      = (const float*)d_in[0];
    const float* ln1_w  = (const float*)d_in[1];
    const float* ln1_b  = (const float*)d_in[2];
    const float* w_attn = (const float*)d_in[3];
    const float* b_attn = (const float*)d_in[4];
    const float* w_proj = (const float*)d_in[5];
    const float* b_proj = (const float*)d_in[6];
    const float* ln2_w  = (const float*)d_in[7];
    const float* ln2_b  = (const float*)d_in[8];
    const float* w_fc   = (const float*)d_in[9];
    const float* b_fc   = (const float*)d_in[10];
    const float* w_fc2  = (const float*)d_in[11];
    const float* b_fc2  = (const float*)d_in[12];
    float* out = (float*)d_out;

    void *px1, *ph, *py, *pfc, *pq, *pkh, *pkl, *pvh, *pvl;
    void *pwah, *pwal, *pwph, *pwpl, *pwfh, *pwfl, *pw2h, *pw2l;
    cudaGetSymbolAddress(&px1, g_x1);
    cudaGetSymbolAddress(&ph,  g_h);
    cudaGetSymbolAddress(&py,  g_y);
    cudaGetSymbolAddress(&pfc, g_fc);
    cudaGetSymbolAddress(&pq,  g_q);
    cudaGetSymbolAddress(&pkh, g_kh);  cudaGetSymbolAddress(&pkl, g_kls);
    cudaGetSymbolAddress(&pvh, g_vh);  cudaGetSymbolAddress(&pvl, g_vls);
    cudaGetSymbolAddress(&pwah, g_wa_h); cudaGetSymbolAddress(&pwal, g_wa_l);
    cudaGetSymbolAddress(&pwph, g_wp_h); cudaGetSymbolAddress(&pwpl, g_wp_l);
    cudaGetSymbolAddress(&pwfh, g_wf_h); cudaGetSymbolAddress(&pwfl, g_wf_l);
    cudaGetSymbolAddress(&pw2h, g_w2_h); cudaGetSymbolAddress(&pw2l, g_w2_l);

    float* x1 = (float*)px1;
    __half* h  = (__half*)ph;
    __half* y  = (__half*)py;
    __half* fc = (__half*)pfc;
    __half* q  = (__half*)pq;
    __half *kh = (__half*)pkh, *kl = (__half*)pkl;
    __half *vh = (__half*)pvh, *vl = (__half*)pvl;
    __half *wah = (__half*)pwah, *wal = (__half*)pwal;
    __half *wph = (__half*)pwph, *wpl = (__half*)pwpl;
    __half *wfh = (__half*)pwfh, *wfl = (__half*)pwfl;
    __half *w2h = (__half*)pw2h, *w2l = (__half*)pw2l;

    static bool attr_done = false;
    if (!attr_done) {
        cudaFuncSetAttribute(mma_gemm<1>, cudaFuncAttributeMaxDynamicSharedMemorySize, GEMM_SMEM);
        cudaFuncSetAttribute(mma_gemm<2>, cudaFuncAttributeMaxDynamicSharedMemorySize, GEMM_SMEM);
        cudaFuncSetAttribute(mma_gemm<3>, cudaFuncAttributeMaxDynamicSharedMemorySize, GEMM_SMEM);
        cudaFuncSetAttribute(attn_mma,    cudaFuncAttributeMaxDynamicSharedMemorySize, ATT_SMEM);
        attr_done = true;
    }

    // 0) weight pre-conversion
    conv_w<<<(Cx*3*Cx/4 + 255)/256, 256>>>(w_attn, wah, wal, Cx*3*Cx/4);
    conv_w<<<(Cx*Cx/4   + 255)/256, 256>>>(w_proj, wph, wpl, Cx*Cx/4);
    conv_w<<<(Cx*4*Cx/4 + 255)/256, 256>>>(w_fc,   wfh, wfl, Cx*4*Cx/4);
    conv_w<<<(4*Cx*Cx/4 + 255)/256, 256>>>(w_fc2,  w2h, w2l, 4*Cx*Cx/4);

    // 1) h = LN1(x)
    ln_kernel<<<Mrows, 256>>>(x, ln1_w, ln1_b, h);
    // 2) QKV GEMM -> q (fp16, x0.125) / k,v (hi+ls), [B,H,L,D]
    mma_gemm<3><<<dim3(3*Cx/128, Mrows/128), 256, GEMM_SMEM>>>(
        h, wah, wal, b_attn, nullptr, nullptr, nullptr,
        q, kh, kl, vh, vl, Mrows, 3*Cx, Cx);
    // 3) y = causal flash attention
    attn_mma<<<dim3(Lx/128, Bsz*Hx), 256, ATT_SMEM>>>(q, kh, kl, vh, vl, y);
    // 4) x1 = x + y @ w_proj + b_proj
    mma_gemm<2><<<dim3(Cx/128, Mrows/128), 256, GEMM_SMEM>>>(
        y, wph, wpl, b_proj, x, x1, nullptr,
        nullptr, nullptr, nullptr, nullptr, nullptr, Mrows, Cx, Cx);
    // 5) h = LN2(x1)
    ln_kernel<<<Mrows, 256>>>(x1, ln2_w, ln2_b, h);
    // 6) fc = gelu(h @ w_fc + b_fc) -> fp16
    mma_gemm<1><<<dim3(4*Cx/128, Mrows/128), 256, GEMM_SMEM>>>(
        h, wfh, wfl, b_fc, nullptr, nullptr, fc,
        nullptr, nullptr, nullptr, nullptr, nullptr, Mrows, 4*Cx, Cx);
    // 7) out = x1 + fc @ w_fc2 + b_fc2
    mma_gemm<2><<<dim3(Cx/128, Mrows/128), 256, GEMM_SMEM>>>(
        fc, w2h, w2l, b_fc2, x1, out, nullptr,
        nullptr, nullptr, nullptr, nullptr, nullptr, Mrows, Cx, 4*Cx);
}

// round 7
// speedup vs baseline: 4.5471x; 1.0845x over previous
#include <cuda_runtime.h>
#include <cuda_fp16.h>
#include <math.h>
#include <stdint.h>

// Problem constants
#define Bsz 2
#define Lx  2048
#define Cx  1024
#define Hx  16
#define Dx  64
#define Mrows (Bsz*Lx)      // 4096

// ---------------- scratch (__device__ globals: alloc-free) ----------------
__device__ float g_x1 [Mrows * Cx];

__device__ __half g_h  [Mrows * Cx];       // LN out (A operand)
__device__ __half g_y  [Mrows * Cx];       // attention out (A operand)
__device__ __half g_fc [Mrows * 4 * Cx];   // gelu out (A operand)

// attention operands, [B,H,L,D]
__device__ __half g_q  [Mrows * Cx];
__device__ __half g_kh [Mrows * Cx];
__device__ __half g_kls[Mrows * Cx];
__device__ __half g_vh [Mrows * Cx];
__device__ __half g_vls[Mrows * Cx];

// weights: hi + scaled lo (concatenated block for single conv kernel)
__device__ __half g_wa_h [Cx * 3 * Cx];
__device__ __half g_wa_l [Cx * 3 * Cx];
__device__ __half g_wp_h [Cx * Cx];
__device__ __half g_wp_l [Cx * Cx];
__device__ __half g_wf_h [Cx * 4 * Cx];
__device__ __half g_wf_l [Cx * 4 * Cx];
__device__ __half g_w2_h [4 * Cx * Cx];
__device__ __half g_w2_l [4 * Cx * Cx];

// ================= helpers ==========================
__device__ __forceinline__ uint32_t smem_u32(const void* p) {
    uint32_t a;
    asm("{ .reg .u64 t; cvta.to.shared.u64 t, %1; cvt.u32.u64 %0, t; }"
        : "=r"(a) : "l"(p));
    return a;
}
__device__ __forceinline__ uint32_t pack_h(float a, float b) {
    __half2 h = __floats2half2_rn(a, b);
    return *(uint32_t*)&h;
}
__device__ __forceinline__ uint32_t pack_ls(float a, float b) {
    float ha = __half2float(__float2half_rn(a));
    float hb = __half2float(__float2half_rn(b));
    __half2 h = __floats2half2_rn((a - ha) * 2048.f, (b - hb) * 2048.f);
    return *(uint32_t*)&h;
}
// multiply packed fp16x2 by 2^-11
__device__ __forceinline__ uint32_t hscale(uint32_t x) {
    uint32_t r;
    asm("mul.rn.f16x2 %0, %1, %2;" : "=r"(r) : "r"(x), "r"(0x10001000u));
    return r;
}

__device__ __forceinline__ void cp16(uint32_t dst, const void* src) {
    asm volatile("cp.async.cg.shared.global [%0], [%1], 16;"
                 :: "r"(dst), "l"(src));
}
#define CP_COMMIT() asm volatile("cp.async.commit_group;" ::: "memory")
#define CP_WAIT1()  asm volatile("cp.async.wait_group 1;" ::: "memory")
#define CP_WAIT2()  asm volatile("cp.async.wait_group 2;" ::: "memory")

__device__ __forceinline__ void ldsm4(uint32_t (&r)[4], uint32_t addr) {
    asm volatile("ldmatrix.sync.aligned.m8n8.x4.shared.b16 {%0,%1,%2,%3}, [%4];"
                 : "=r"(r[0]), "=r"(r[1]), "=r"(r[2]), "=r"(r[3]) : "r"(addr));
}
__device__ __forceinline__ void ldsm4t(uint32_t (&r)[4], uint32_t addr) {
    asm volatile("ldmatrix.sync.aligned.m8n8.x4.trans.shared.b16 {%0,%1,%2,%3}, [%4];"
                 : "=r"(r[0]), "=r"(r[1]), "=r"(r[2]), "=r"(r[3]) : "r"(addr));
}
__device__ __forceinline__ void mma_f16(float (&c)[4], const uint32_t (&a)[4],
                                        uint32_t b0, uint32_t b1) {
    asm volatile(
        "mma.sync.aligned.m16n8k16.row.col.f32.f16.f16.f32 "
        "{%0,%1,%2,%3},{%4,%5,%6,%7},{%8,%9},{%0,%1,%2,%3};"
        : "+f"(c[0]), "+f"(c[1]), "+f"(c[2]), "+f"(c[3])
        : "r"(a[0]), "r"(a[1]), "r"(a[2]), "r"(a[3]), "r"(b0), "r"(b1));
}

__device__ __forceinline__ float gelu_f(float x) {
    float x3 = x * x * x;
    float t  = tanhf(0.7978845608028654f * (x + 0.044715f * x3));
    return 0.5f * x * (1.0f + t);
}

// exp2 on the FMA pipe
__device__ __forceinline__ float pexp2(float t) {
    t = fmaxf(t, -126.f);
    float k  = t + 12582912.f;
    int   i  = __float_as_int(k) - 0x4B400000;
    float fi = k - 12582912.f;
    float f  = t - fi;
    float p  = 1.3333558e-3f;
    p = fmaf(p, f, 9.6181291e-3f);
    p = fmaf(p, f, 5.5504109e-2f);
    p = fmaf(p, f, 2.4022651e-1f);
    p = fmaf(p, f, 6.9314718e-1f);
    p = fmaf(p, f, 1.0f);
    return __int_as_float(__float_as_int(p) + (i << 23));
}
#define LOG2E 1.4426950408889634f

// -------- single-launch weight conversion (4 weights, segmented) ----------
#define N4_WA 786432    // 1024*3072/4
#define N4_WP 262144    // 1024*1024/4
#define N4_WF 1048576   // 1024*4096/4
#define N4_W2 1048576   // 4096*1024/4
#define N4_TOT (N4_WA + N4_WP + N4_WF + N4_W2)   // 3145728

__global__ __launch_bounds__(256) void conv_all(
    const float* __restrict__ wa, const float* __restrict__ wp,
    const float* __restrict__ wf, const float* __restrict__ w2)
{
    int i = blockIdx.x * 256 + threadIdx.x;
    if (i >= N4_TOT) return;
    const float* src;
    __half *hi, *ls;
    int j = i;
    if (j < N4_WA) {
        src = wa; hi = g_wa_h; ls = g_wa_l;
    } else if ((j -= N4_WA) < N4_WP) {
        src = wp; hi = g_wp_h; ls = g_wp_l;
    } else if ((j -= N4_WP) < N4_WF) {
        src = wf; hi = g_wf_h; ls = g_wf_l;
    } else {
        j -= N4_WF;
        src = w2; hi = g_w2_h; ls = g_w2_l;
    }
    float4 v = ((const float4*)src)[j];
    ((uint2*)hi)[j] = make_uint2(pack_h(v.x, v.y),  pack_h(v.z, v.w));
    ((uint2*)ls)[j] = make_uint2(pack_ls(v.x, v.y), pack_ls(v.z, v.w));
}

// =========================================================================
// 2-term split-fp16 GEMM, 3-stage pipeline, 2 CTAs/SM.
// EPI: 1 = bias+gelu -> fp16; 2 = bias+residual -> fp32
//      3 = bias, split Q(x0.125)/K(h,ls)/V(h,ls) in [B,H,L,D]
// =========================================================================
#define A_STRIDE 80
#define B_STRIDE 272
#define SZ_A (128 * A_STRIDE)          // 10240
#define SZ_B (32 * B_STRIDE)           // 8704
#define OFF_B  SZ_A
#define STAGE_BYTES (SZ_A + 2 * SZ_B)  // 27648
#define GEMM_SMEM (3 * STAGE_BYTES)    // 82944 -> 2 CTAs/SM

template<int EPI>
__global__ __launch_bounds__(256, 2) void mma_gemm(
    const __half* __restrict__ A,
    const __half* __restrict__ Wh, const __half* __restrict__ Wls,
    const float* __restrict__ bias, const float* __restrict__ res,
    float* __restrict__ outf, __half* __restrict__ outh,
    __half* __restrict__ q_, __half* __restrict__ kh_, __half* __restrict__ kls_,
    __half* __restrict__ vh_, __half* __restrict__ vls_,
    int M, int N, int K)
{
    extern __shared__ char smem_raw[];
    const uint32_t sm = smem_u32(smem_raw);

    const int tid  = threadIdx.x;
    const int wid  = tid >> 5;
    const int lane = tid & 31;
    const int bm   = blockIdx.y * 128;
    const int bn   = blockIdx.x * 128;
    const int wm   = wid >> 2;
    const int wn   = wid & 3;
    const int nch  = K >> 5;

    float acc[4][4][4];
    #pragma unroll
    for (int i = 0; i < 4; i++)
        #pragma unroll
        for (int j = 0; j < 4; j++)
            #pragma unroll
            for (int q = 0; q < 4; q++) acc[i][j][q] = 0.f;

    auto load_stage = [&](int c) {
        if (c < nch) {
            const int s  = c % 3;
            const int k0 = c << 5;
            const uint32_t sb = sm + s * STAGE_BYTES;
            #pragma unroll
            for (int u = 0; u < 2; u++) {
                int f   = u * 256 + tid;
                int row = f >> 2, seg = f & 3;
                cp16(sb + row * A_STRIDE + seg * 16,
                     A + (size_t)(bm + row) * K + k0 + seg * 8);
            }
            #pragma unroll
            for (int j = 0; j < 2; j++) {
                const __half* src = (j == 0) ? Wh : Wls;
                #pragma unroll
                for (int u = 0; u < 2; u++) {
                    int i  = u * 256 + tid;
                    int kr = i >> 4, seg = i & 15;
                    cp16(sb + OFF_B + j * SZ_B + kr * B_STRIDE + seg * 16,
                         src + (size_t)(k0 + kr) * N + bn + seg * 8);
                }
            }
        }
        CP_COMMIT();
    };

    load_stage(0);
    load_stage(1);

    const int lr = lane & 15;
    const int lc = lane >> 4;

    for (int c = 0; c < nch; c++) {
        load_stage(c + 2);       // writes stage (c+2)%3: disjoint from c, c+1
        CP_WAIT2();              // stage c complete
        __syncthreads();

        const uint32_t sb = sm + (c % 3) * STAGE_BYTES;

        #pragma unroll
        for (int ks = 0; ks < 2; ks++) {
            uint32_t ah[4][4], as[4][4];
            #pragma unroll
            for (int mf = 0; mf < 4; mf++) {
                uint32_t ao = sb + (wm * 64 + mf * 16 + lr) * A_STRIDE
                            + lc * 16 + ks * 32;
                ldsm4(ah[mf], ao);
                #pragma unroll
                for (int r = 0; r < 4; r++) as[mf][r] = hscale(ah[mf][r]);
            }
            #pragma unroll
            for (int nt = 0; nt < 2; nt++) {
                uint32_t bh4[4], bl4[4];
                uint32_t bo = sb + OFF_B + (ks * 16 + lr) * B_STRIDE
                            + (wn * 32 + nt * 16 + lc * 8) * 2;
                ldsm4t(bh4, bo);
                ldsm4t(bl4, bo + SZ_B);
                #pragma unroll
                for (int mf = 0; mf < 4; mf++) {
                    mma_f16(acc[mf][nt*2],   ah[mf], bh4[0], bh4[1]);
                    mma_f16(acc[mf][nt*2],   as[mf], bl4[0], bl4[1]);
                    mma_f16(acc[mf][nt*2+1], ah[mf], bh4[2], bh4[3]);
                    mma_f16(acc[mf][nt*2+1], as[mf], bl4[2], bl4[3]);
                }
            }
        }
        __syncthreads();
    }

    // ---- epilogue ----
    #pragma unroll
    for (int mf = 0; mf < 4; mf++) {
        #pragma unroll
        for (int nf = 0; nf < 4; nf++) {
            int col = bn + wn * 32 + nf * 8 + (lane & 3) * 2;
            float2 bv = *(const float2*)(bias + col);
            #pragma unroll
            for (int half = 0; half < 2; half++) {
                int row = bm + wm * 64 + mf * 16 + (lane >> 2) + half * 8;
                float v0 = acc[mf][nf][half * 2 + 0] + bv.x;
                float v1 = acc[mf][nf][half * 2 + 1] + bv.y;
                if (EPI == 1) {
                    v0 = gelu_f(v0); v1 = gelu_f(v1);
                    *(uint32_t*)(outh + (size_t)row * N + col) = pack_h(v0, v1);
                } else if (EPI == 3) {
                    int sector = col >> 10;
                    int wcol = col & 1023;
                    int hh = wcol >> 6;
                    int dd = wcol & 63;
                    int brow = row >> 11;
                    int lrow = row & 2047;
                    size_t dst = ((size_t)(brow * Hx + hh) * Lx + lrow) * Dx + dd;
                    if (sector == 0) {
                        *(uint32_t*)(q_ + dst) = pack_h(v0 * 0.125f, v1 * 0.125f);
                    } else if (sector == 1) {
                        *(uint32_t*)(kh_  + dst) = pack_h(v0, v1);
                        *(uint32_t*)(kls_ + dst) = pack_ls(v0, v1);
                    } else {
                        *(uint32_t*)(vh_  + dst) = pack_h(v0, v1);
                        *(uint32_t*)(vls_ + dst) = pack_ls(v0, v1);
                    }
                } else {
                    float2 rv = *(const float2*)(res + (size_t)row * N + col);
                    v0 += rv.x; v1 += rv.y;
                    *(float2*)(outf + (size_t)row * N + col) = make_float2(v0, v1);
                }
            }
        }
    }
}

// ---------------- LayerNorm -> fp16 output --------------------------------
__global__ __launch_bounds__(256) void ln_kernel(const float* __restrict__ x,
                                                 const float* __restrict__ w,
                                                 const float* __restrict__ b,
                                                 __half* __restrict__ oh)
{
    int row = blockIdx.x;
    int t   = threadIdx.x;
    const float4* xr = (const float4*)(x + (size_t)row * Cx);
    float4 v = xr[t];
    float s  = v.x + v.y + v.z + v.w;
    float sq = v.x*v.x + v.y*v.y + v.z*v.z + v.w*v.w;
    #pragma unroll
    for (int o = 16; o > 0; o >>= 1) {
        s  += __shfl_xor_sync(0xffffffffu, s,  o);
        sq += __shfl_xor_sync(0xffffffffu, sq, o);
    }
    __shared__ float ss[8], ssq[8];
    int wid = t >> 5, lane = t & 31;
    if (lane == 0) { ss[wid] = s; ssq[wid] = sq; }
    __syncthreads();
    float tot = 0.f, totq = 0.f;
    #pragma unroll
    for (int i = 0; i < 8; i++) { tot += ss[i]; totq += ssq[i]; }
    float mean = tot * (1.0f / Cx);
    float var  = totq * (1.0f / Cx) - mean * mean;
    float rstd = rsqrtf(var + 1e-5f);
    const float4 wv = ((const float4*)w)[t];
    const float4 bv = ((const float4*)b)[t];
    float o0 = (v.x - mean) * rstd * wv.x + bv.x;
    float o1 = (v.y - mean) * rstd * wv.y + bv.y;
    float o2 = (v.z - mean) * rstd * wv.z + bv.z;
    float o3 = (v.w - mean) * rstd * wv.w + bv.w;
    size_t idx = (size_t)row * Cx + t * 4;
    *(uint2*)(oh + idx) = make_uint2(pack_h(o0, o1), pack_h(o2, o3));
}

// =========================================================================
// Tensor-core causal flash attention, 2-term split-fp16 (as R5, passing).
// =========================================================================
#define QSTR 144
#define ATT_QS   18432
#define ATT_KVS  9216
#define ATT_STG  (4*ATT_KVS)
#define ATT_SMEM (ATT_QS + 3*ATT_STG)  // 129024

__global__ __launch_bounds__(256, 1) void attn_mma(
    const __half* __restrict__ q_,
    const __half* __restrict__ kh_, const __half* __restrict__ kls_,
    const __half* __restrict__ vh_, const __half* __restrict__ vls_,
    __half* __restrict__ y_)
{
    extern __shared__ char sm_raw[];
    const uint32_t S = smem_u32(sm_raw);
    const int tid = threadIdx.x, wid = tid >> 5, lane = tid & 31;
    const int qt  = gridDim.x - 1 - blockIdx.x;
    const int qb  = qt * 128;
    const int bh  = blockIdx.y;
    const size_t hb = (size_t)bh * Lx * Dx;

    const __half *Q  = q_  + hb;
    const __half *Kh = kh_ + hb, *Kl = kls_ + hb;
    const __half *Vh = vh_ + hb, *Vl = vls_ + hb;

    const int nk = 2 * qt + 2;

    auto load_kv = [&](int kt) {
        if (kt < nk) {
            const uint32_t db = S + ATT_QS + (kt % 3) * ATT_STG;
            #pragma unroll
            for (int u = 0; u < 8; u++) {
                int j = u * 256 + tid;
                int arr = j >> 9;
                int rem = j & 511;
                int row = rem >> 3, seg = rem & 7;
                const __half* src = (arr == 0) ? Kh : (arr == 1) ? Kl
                                   : (arr == 2) ? Vh : Vl;
                cp16(db + arr * ATT_KVS + row * QSTR + seg * 16,
                     src + (size_t)(kt * 64 + row) * Dx + seg * 8);
            }
        }
        CP_COMMIT();
    };

    #pragma unroll
    for (int u = 0; u < 4; u++) {
        int j = u * 256 + tid;
        int row = j >> 3, seg = j & 7;
        cp16(S + row * QSTR + seg * 16,
             Q + (size_t)(qb + row) * Dx + seg * 8);
    }
    {
        const uint32_t db = S + ATT_QS;
        #pragma unroll
        for (int u = 0; u < 8; u++) {
            int j = u * 256 + tid;
            int arr = j >> 9;
            int rem = j & 511;
            int row = rem >> 3, seg = rem & 7;
            const __half* src = (arr == 0) ? Kh : (arr == 1) ? Kl
                               : (arr == 2) ? Vh : Vl;
            cp16(db + arr * ATT_KVS + row * QSTR + seg * 16,
                 src + (size_t)row * Dx + seg * 8);
        }
        CP_COMMIT();
    }
    load_kv(1);

    uint32_t qf[4][4], qs[4][4];
    float oc[8][4];
    #pragma unroll
    for (int d = 0; d < 8; d++)
        #pragma unroll
        for (int i = 0; i < 4; i++) oc[d][i] = 0.f;
    float m0 = -1e30f, m1 = -1e30f, l0 = 0.f, l1 = 0.f;

    const int wrow_min = qb + wid * 16;
    const int r0g = wrow_min + (lane >> 2);

    for (int kt = 0; kt < nk; kt++) {
        CP_WAIT1();
        __syncthreads();
        if (kt == 0) {
            #pragma unroll
            for (int ks = 0; ks < 4; ks++) {
                uint32_t ao = S + (wid * 16 + (lane & 15)) * QSTR
                            + (lane >> 4) * 16 + ks * 32;
                ldsm4(qf[ks], ao);
                #pragma unroll
                for (int r = 0; r < 4; r++) qs[ks][r] = hscale(qf[ks][r]);
            }
        }
        load_kv(kt + 2);

        const int k0 = kt * 64;
        if (k0 <= wrow_min + 15) {
            const uint32_t kb = S + ATT_QS + (kt % 3) * ATT_STG;

            float sc[8][4];
            #pragma unroll
            for (int nt = 0; nt < 8; nt++)
                #pragma unroll
                for (int i = 0; i < 4; i++) sc[nt][i] = 0.f;

            #pragma unroll
            for (int ks = 0; ks < 4; ks++) {
                uint32_t k4[4][4], kl4[4][4];
                #pragma unroll
                for (int ntp = 0; ntp < 4; ntp++) {
                    uint32_t ad = kb
                        + (uint32_t)((ntp * 16 + (lane & 7) + ((lane >> 4) << 3)) * QSTR)
                        + ((lane >> 3) & 1) * 16 + ks * 32;
                    ldsm4(k4[ntp], ad);
                    ldsm4(kl4[ntp], ad + ATT_KVS);
                }
                #pragma unroll
                for (int ntp = 0; ntp < 4; ntp++)
                    #pragma unroll
                    for (int hf = 0; hf < 2; hf++) {
                        int nt = ntp * 2 + hf, p = hf * 2;
                        mma_f16(sc[nt], qf[ks], k4[ntp][p],  k4[ntp][p + 1]);
                        mma_f16(sc[nt], qs[ks], kl4[ntp][p], kl4[ntp][p + 1]);
                    }
            }

            if (k0 + 63 > wrow_min) {
                #pragma unroll
                for (int nt = 0; nt < 8; nt++) {
                    int key = k0 + nt * 8 + (lane & 3) * 2;
                    if (key     > r0g)     sc[nt][0] = -1e30f;
                    if (key + 1 > r0g)     sc[nt][1] = -1e30f;
                    if (key     > r0g + 8) sc[nt][2] = -1e30f;
                    if (key + 1 > r0g + 8) sc[nt][3] = -1e30f;
                }
            }

            float rm0 = -1e30f, rm1 = -1e30f;
            #pragma unroll
            for (int nt = 0; nt < 8; nt++) {
                rm0 = fmaxf(rm0, fmaxf(sc[nt][0], sc[nt][1]));
                rm1 = fmaxf(rm1, fmaxf(sc[nt][2], sc[nt][3]));
            }
            rm0 = fmaxf(rm0, __shfl_xor_sync(0xffffffffu, rm0, 1));
            rm0 = fmaxf(rm0, __shfl_xor_sync(0xffffffffu, rm0, 2));
            rm1 = fmaxf(rm1, __shfl_xor_sync(0xffffffffu, rm1, 1));
            rm1 = fmaxf(rm1, __shfl_xor_sync(0xffffffffu, rm1, 2));
            float mn0 = fmaxf(m0, rm0 * LOG2E);
            float mn1 = fmaxf(m1, rm1 * LOG2E);
            float s0 = pexp2(m0 - mn0);
            float s1 = pexp2(m1 - mn1);
            m0 = mn0; m1 = mn1;
            l0 *= s0; l1 *= s1;
            #pragma unroll
            for (int d = 0; d < 8; d++) {
                oc[d][0] *= s0; oc[d][1] *= s0;
                oc[d][2] *= s1; oc[d][3] *= s1;
            }

            uint32_t pa[4][4], pas[4][4];
            float la0 = 0.f, la1 = 0.f;
            #pragma unroll
            for (int nt = 0; nt < 8; nt++) {
                float p0 = pexp2(fmaf(sc[nt][0], LOG2E, -m0));
                float p1 = pexp2(fmaf(sc[nt][1], LOG2E, -m0));
                float p2 = pexp2(fmaf(sc[nt][2], LOG2E, -m1));
                float p3 = pexp2(fmaf(sc[nt][3], LOG2E, -m1));
                la0 += p0 + p1;
                la1 += p2 + p3;
                int ks2 = nt >> 1, idx = (nt & 1) * 2;
                pa[ks2][idx]     = pack_h(p0, p1);
                pa[ks2][idx + 1] = pack_h(p2, p3);
            }
            l0 += la0; l1 += la1;
            #pragma unroll
            for (int ks2 = 0; ks2 < 4; ks2++)
                #pragma unroll
                for (int r = 0; r < 4; r++) pas[ks2][r] = hscale(pa[ks2][r]);

            #pragma unroll
            for (int ks2 = 0; ks2 < 4; ks2++) {
                uint32_t v4[4][4], vl4[4][4];
                #pragma unroll
                for (int dtp = 0; dtp < 4; dtp++) {
                    uint32_t ad = kb + 2 * ATT_KVS
                        + (uint32_t)((ks2 * 16 + (lane & 15)) * QSTR)
                        + (dtp * 16 + (lane >> 4) * 8) * 2;
                    ldsm4t(v4[dtp], ad);
                    ldsm4t(vl4[dtp], ad + ATT_KVS);
                }
                #pragma unroll
                for (int dtp = 0; dtp < 4; dtp++)
                    #pragma unroll
                    for (int hf = 0; hf < 2; hf++) {
                        int dt = dtp * 2 + hf, p = hf * 2;
                        mma_f16(oc[dt], pa[ks2],  v4[dtp][p],  v4[dtp][p + 1]);
                        mma_f16(oc[dt], pas[ks2], vl4[dtp][p], vl4[dtp][p + 1]);
                    }
            }
        }
    }

    l0 += __shfl_xor_sync(0xffffffffu, l0, 1);
    l0 += __shfl_xor_sync(0xffffffffu, l0, 2);
    l1 += __shfl_xor_sync(0xffffffffu, l1, 1);
    l1 += __shfl_xor_sync(0xffffffffu, l1, 2);
    float i0 = 1.f / l0, i1 = 1.f / l1;

    const int b  = bh >> 4;
    const int hh = bh & 15;
    const size_t row0 = (size_t)b * Lx + qb + wid * 16 + (lane >> 2);
    const int colb = hh * 64 + (lane & 3) * 2;
    #pragma unroll
    for (int dt = 0; dt < 8; dt++) {
        float a0 = oc[dt][0] * i0, a1 = oc[dt][1] * i0;
        float a2 = oc[dt][2] * i1, a3 = oc[dt][3] * i1;
        *(uint32_t*)(y_ + row0 * Cx + colb + dt * 8)       = pack_h(a0, a1);
        *(uint32_t*)(y_ + (row0 + 8) * Cx + colb + dt * 8) = pack_h(a2, a3);
    }
}

// ---------------- launcher ----------------
extern "C" void kernel_launch(void* const* d_in, const int* in_sizes, int n_in,
                              void* d_out, int out_size)
{
    const float* x      = (const float*)d_in[0];
    const float* ln1_w  = (const float*)d_in[1];
    const float* ln1_b  = (const float*)d_in[2];
    const float* w_attn = (const float*)d_in[3];
    const float* b_attn = (const float*)d_in[4];
    const float* w_proj = (const float*)d_in[5];
    const float* b_proj = (const float*)d_in[6];
    const float* ln2_w  = (const float*)d_in[7];
    const float* ln2_b  = (const float*)d_in[8];
    const float* w_fc   = (const float*)d_in[9];
    const float* b_fc   = (const float*)d_in[10];
    const float* w_fc2  = (const float*)d_in[11];
    const float* b_fc2  = (const float*)d_in[12];
    float* out = (float*)d_out;

    void *px1, *ph, *py, *pfc, *pq, *pkh, *pkl, *pvh, *pvl;
    void *pwah, *pwal, *pwph, *pwpl, *pwfh, *pwfl, *pw2h, *pw2l;
    cudaGetSymbolAddress(&px1, g_x1);
    cudaGetSymbolAddress(&ph,  g_h);
    cudaGetSymbolAddress(&py,  g_y);
    cudaGetSymbolAddress(&pfc, g_fc);
    cudaGetSymbolAddress(&pq,  g_q);
    cudaGetSymbolAddress(&pkh, g_kh);  cudaGetSymbolAddress(&pkl, g_kls);
    cudaGetSymbolAddress(&pvh, g_vh);  cudaGetSymbolAddress(&pvl, g_vls);
    cudaGetSymbolAddress(&pwah, g_wa_h); cudaGetSymbolAddress(&pwal, g_wa_l);
    cudaGetSymbolAddress(&pwph, g_wp_h); cudaGetSymbolAddress(&pwpl, g_wp_l);
    cudaGetSymbolAddress(&pwfh, g_wf_h); cudaGetSymbolAddress(&pwfl, g_wf_l);
    cudaGetSymbolAddress(&pw2h, g_w2_h); cudaGetSymbolAddress(&pw2l, g_w2_l);

    float* x1 = (float*)px1;
    __half* h  = (__half*)ph;
    __half* y  = (__half*)py;
    __half* fc = (__half*)pfc;
    __half* q  = (__half*)pq;
    __half *kh = (__half*)pkh, *kl = (__half*)pkl;
    __half *vh = (__half*)pvh, *vl = (__half*)pvl;
    __half *wah = (__half*)pwah, *wal = (__half*)pwal;
    __half *wph = (__half*)pwph, *wpl = (__half*)pwpl;
    __half *wfh = (__half*)pwfh, *wfl = (__half*)pwfl;
    __half *w2h = (__half*)pw2h, *w2l = (__half*)pw2l;

    static bool attr_done = false;
    if (!attr_done) {
        cudaFuncSetAttribute(mma_gemm<1>, cudaFuncAttributeMaxDynamicSharedMemorySize, GEMM_SMEM);
        cudaFuncSetAttribute(mma_gemm<2>, cudaFuncAttributeMaxDynamicSharedMemorySize, GEMM_SMEM);
        cudaFuncSetAttribute(mma_gemm<3>, cudaFuncAttributeMaxDynamicSharedMemorySize, GEMM_SMEM);
        cudaFuncSetAttribute(attn_mma,    cudaFuncAttributeMaxDynamicSharedMemorySize, ATT_SMEM);
        attr_done = true;
    }

    // 0) weight pre-conversion (one launch)
    conv_all<<<(N4_TOT + 255)/256, 256>>>(w_attn, w_proj, w_fc, w_fc2);

    // 1) h = LN1(x)
    ln_kernel<<<Mrows, 256>>>(x, ln1_w, ln1_b, h);
    // 2) QKV GEMM -> q (fp16, x0.125) / k,v (hi+ls), [B,H,L,D]
    mma_gemm<3><<<dim3(3*Cx/128, Mrows/128), 256, GEMM_SMEM>>>(
        h, wah, wal, b_attn, nullptr, nullptr, nullptr,
        q, kh, kl, vh, vl, Mrows, 3*Cx, Cx);
    // 3) y = causal flash attention
    attn_mma<<<dim3(Lx/128, Bsz*Hx), 256, ATT_SMEM>>>(q, kh, kl, vh, vl, y);
    // 4) x1 = x + y @ w_proj + b_proj
    mma_gemm<2><<<dim3(Cx/128, Mrows/128), 256, GEMM_SMEM>>>(
        y, wph, wpl, b_proj, x, x1, nullptr,
        nullptr, nullptr, nullptr, nullptr, nullptr, Mrows, Cx, Cx);
    // 5) h = LN2(x1)
    ln_kernel<<<Mrows, 256>>>(x1, ln2_w, ln2_b, h);
    // 6) fc = gelu(h @ w_fc + b_fc) -> fp16
    mma_gemm<1><<<dim3(4*Cx/128, Mrows/128), 256, GEMM_SMEM>>>(
        h, wfh, wfl, b_fc, nullptr, nullptr, fc,
        nullptr, nullptr, nullptr, nullptr, nullptr, Mrows, 4*Cx, Cx);
    // 7) out = x1 + fc @ w_fc2 + b_fc2
    mma_gemm<2><<<dim3(Cx/128, Mrows/128), 256, GEMM_SMEM>>>(
        fc, w2h, w2l, b_fc2, x1, out, nullptr,
        nullptr, nullptr, nullptr, nullptr, nullptr, Mrows, Cx, 4*Cx);
}

// round 8
// speedup vs baseline: 4.7834x; 1.0520x over previous
#include <cuda_runtime.h>
#include <cuda_fp16.h>
#include <math.h>
#include <stdint.h>

// Problem constants
#define Bsz 2
#define Lx  2048
#define Cx  1024
#define Hx  16
#define Dx  64
#define Mrows (Bsz*Lx)      // 4096

// ---------------- scratch (__device__ globals: alloc-free) ----------------
__device__ float g_x1 [Mrows * Cx];

__device__ __half g_h  [Mrows * Cx];
__device__ __half g_y  [Mrows * Cx];
__device__ __half g_fc [Mrows * 4 * Cx];

// attention operands, [B,H,L,D]
__device__ __half g_q  [Mrows * Cx];
__device__ __half g_kh [Mrows * Cx];
__device__ __half g_kls[Mrows * Cx];
__device__ __half g_vh [Mrows * Cx];
__device__ __half g_vls[Mrows * Cx];

// weights: hi + scaled lo
__device__ __half g_wa_h [Cx * 3 * Cx];
__device__ __half g_wa_l [Cx * 3 * Cx];
__device__ __half g_wp_h [Cx * Cx];
__device__ __half g_wp_l [Cx * Cx];
__device__ __half g_wf_h [Cx * 4 * Cx];
__device__ __half g_wf_l [Cx * 4 * Cx];
__device__ __half g_w2_h [4 * Cx * Cx];
__device__ __half g_w2_l [4 * Cx * Cx];

// ================= helpers ==========================
__device__ __forceinline__ uint32_t smem_u32(const void* p) {
    uint32_t a;
    asm("{ .reg .u64 t; cvta.to.shared.u64 t, %1; cvt.u32.u64 %0, t; }"
        : "=r"(a) : "l"(p));
    return a;
}
__device__ __forceinline__ uint32_t pack_h(float a, float b) {
    __half2 h = __floats2half2_rn(a, b);
    return *(uint32_t*)&h;
}
__device__ __forceinline__ uint32_t pack_ls(float a, float b) {
    float ha = __half2float(__float2half_rn(a));
    float hb = __half2float(__float2half_rn(b));
    __half2 h = __floats2half2_rn((a - ha) * 2048.f, (b - hb) * 2048.f);
    return *(uint32_t*)&h;
}
__device__ __forceinline__ uint32_t hscale(uint32_t x) {
    uint32_t r;
    asm("mul.rn.f16x2 %0, %1, %2;" : "=r"(r) : "r"(x), "r"(0x10001000u));
    return r;
}

__device__ __forceinline__ void cp16(uint32_t dst, const void* src) {
    asm volatile("cp.async.cg.shared.global [%0], [%1], 16;"
                 :: "r"(dst), "l"(src));
}
#define CP_COMMIT() asm volatile("cp.async.commit_group;" ::: "memory")
#define CP_WAIT0()  asm volatile("cp.async.wait_group 0;" ::: "memory")
#define CP_WAIT1()  asm volatile("cp.async.wait_group 1;" ::: "memory")

__device__ __forceinline__ void ldsm4(uint32_t (&r)[4], uint32_t addr) {
    asm volatile("ldmatrix.sync.aligned.m8n8.x4.shared.b16 {%0,%1,%2,%3}, [%4];"
                 : "=r"(r[0]), "=r"(r[1]), "=r"(r[2]), "=r"(r[3]) : "r"(addr));
}
__device__ __forceinline__ void ldsm4t(uint32_t (&r)[4], uint32_t addr) {
    asm volatile("ldmatrix.sync.aligned.m8n8.x4.trans.shared.b16 {%0,%1,%2,%3}, [%4];"
                 : "=r"(r[0]), "=r"(r[1]), "=r"(r[2]), "=r"(r[3]) : "r"(addr));
}
__device__ __forceinline__ void mma_f16(float (&c)[4], const uint32_t (&a)[4],
                                        uint32_t b0, uint32_t b1) {
    asm volatile(
        "mma.sync.aligned.m16n8k16.row.col.f32.f16.f16.f32 "
        "{%0,%1,%2,%3},{%4,%5,%6,%7},{%8,%9},{%0,%1,%2,%3};"
        : "+f"(c[0]), "+f"(c[1]), "+f"(c[2]), "+f"(c[3])
        : "r"(a[0]), "r"(a[1]), "r"(a[2]), "r"(a[3]), "r"(b0), "r"(b1));
}

__device__ __forceinline__ float gelu_f(float x) {
    float x3 = x * x * x;
    float t  = tanhf(0.7978845608028654f * (x + 0.044715f * x3));
    return 0.5f * x * (1.0f + t);
}

// exp2 on the FMA pipe
__device__ __forceinline__ float pexp2(float t) {
    t = fmaxf(t, -126.f);
    float k  = t + 12582912.f;
    int   i  = __float_as_int(k) - 0x4B400000;
    float fi = k - 12582912.f;
    float f  = t - fi;
    float p  = 1.3333558e-3f;
    p = fmaf(p, f, 9.6181291e-3f);
    p = fmaf(p, f, 5.5504109e-2f);
    p = fmaf(p, f, 2.4022651e-1f);
    p = fmaf(p, f, 6.9314718e-1f);
    p = fmaf(p, f, 1.0f);
    return __int_as_float(__float_as_int(p) + (i << 23));
}
#define LOG2E 1.4426950408889634f

// -------- single-launch weight conversion ---------------------------------
#define N4_WA 786432
#define N4_WP 262144
#define N4_WF 1048576
#define N4_W2 1048576
#define N4_TOT (N4_WA + N4_WP + N4_WF + N4_W2)

__global__ __launch_bounds__(256) void conv_all(
    const float* __restrict__ wa, const float* __restrict__ wp,
    const float* __restrict__ wf, const float* __restrict__ w2)
{
    int i = blockIdx.x * 256 + threadIdx.x;
    if (i >= N4_TOT) return;
    const float* src;
    __half *hi, *ls;
    int j = i;
    if (j < N4_WA) {
        src = wa; hi = g_wa_h; ls = g_wa_l;
    } else if ((j -= N4_WA) < N4_WP) {
        src = wp; hi = g_wp_h; ls = g_wp_l;
    } else if ((j -= N4_WP) < N4_WF) {
        src = wf; hi = g_wf_h; ls = g_wf_l;
    } else {
        j -= N4_WF;
        src = w2; hi = g_w2_h; ls = g_w2_l;
    }
    float4 v = ((const float4*)src)[j];
    ((uint2*)hi)[j] = make_uint2(pack_h(v.x, v.y),  pack_h(v.z, v.w));
    ((uint2*)ls)[j] = make_uint2(pack_ls(v.x, v.y), pack_ls(v.z, v.w));
}

// =========================================================================
// 2-term split-fp16 GEMM, 3-stage pipeline, single sync per chunk, 2 CTA/SM
// =========================================================================
#define A_STRIDE 80
#define B_STRIDE 272
#define SZ_A (128 * A_STRIDE)
#define SZ_B (32 * B_STRIDE)
#define OFF_B  SZ_A
#define STAGE_BYTES (SZ_A + 2 * SZ_B)  // 27648
#define GEMM_SMEM (3 * STAGE_BYTES)    // 82944

template<int EPI>
__global__ __launch_bounds__(256, 2) void mma_gemm(
    const __half* __restrict__ A,
    const __half* __restrict__ Wh, const __half* __restrict__ Wls,
    const float* __restrict__ bias, const float* __restrict__ res,
    float* __restrict__ outf, __half* __restrict__ outh,
    __half* __restrict__ q_, __half* __restrict__ kh_, __half* __restrict__ kls_,
    __half* __restrict__ vh_, __half* __restrict__ vls_,
    int M, int N, int K)
{
    extern __shared__ char smem_raw[];
    const uint32_t sm = smem_u32(smem_raw);

    const int tid  = threadIdx.x;
    const int wid  = tid >> 5;
    const int lane = tid & 31;
    const int bm   = blockIdx.y * 128;
    const int bn   = blockIdx.x * 128;
    const int wm   = wid >> 2;
    const int wn   = wid & 3;
    const int nch  = K >> 5;

    float acc[4][4][4];
    #pragma unroll
    for (int i = 0; i < 4; i++)
        #pragma unroll
        for (int j = 0; j < 4; j++)
            #pragma unroll
            for (int q = 0; q < 4; q++) acc[i][j][q] = 0.f;

    auto load_stage = [&](int c) {
        if (c < nch) {
            const int s  = c % 3;
            const int k0 = c << 5;
            const uint32_t sb = sm + s * STAGE_BYTES;
            #pragma unroll
            for (int u = 0; u < 2; u++) {
                int f   = u * 256 + tid;
                int row = f >> 2, seg = f & 3;
                cp16(sb + row * A_STRIDE + seg * 16,
                     A + (size_t)(bm + row) * K + k0 + seg * 8);
            }
            #pragma unroll
            for (int j = 0; j < 2; j++) {
                const __half* src = (j == 0) ? Wh : Wls;
                #pragma unroll
                for (int u = 0; u < 2; u++) {
                    int i  = u * 256 + tid;
                    int kr = i >> 4, seg = i & 15;
                    cp16(sb + OFF_B + j * SZ_B + kr * B_STRIDE + seg * 16,
                         src + (size_t)(k0 + kr) * N + bn + seg * 8);
                }
            }
        }
        CP_COMMIT();
    };

    load_stage(0);
    load_stage(1);

    const int lr = lane & 15;
    const int lc = lane >> 4;

    for (int c = 0; c < nch; c++) {
        CP_WAIT1();              // stage c landed (c+1 may be pending)
        __syncthreads();         // all warps done with compute(c-1)
        load_stage(c + 2);       // writes (c+2)%3 == (c-1)%3: safe after sync

        const uint32_t sb = sm + (c % 3) * STAGE_BYTES;

        #pragma unroll
        for (int ks = 0; ks < 2; ks++) {
            uint32_t ah[4][4], as[4][4];
            #pragma unroll
            for (int mf = 0; mf < 4; mf++) {
                uint32_t ao = sb + (wm * 64 + mf * 16 + lr) * A_STRIDE
                            + lc * 16 + ks * 32;
                ldsm4(ah[mf], ao);
                #pragma unroll
                for (int r = 0; r < 4; r++) as[mf][r] = hscale(ah[mf][r]);
            }
            #pragma unroll
            for (int nt = 0; nt < 2; nt++) {
                uint32_t bh4[4], bl4[4];
                uint32_t bo = sb + OFF_B + (ks * 16 + lr) * B_STRIDE
                            + (wn * 32 + nt * 16 + lc * 8) * 2;
                ldsm4t(bh4, bo);
                ldsm4t(bl4, bo + SZ_B);
                #pragma unroll
                for (int mf = 0; mf < 4; mf++) {
                    mma_f16(acc[mf][nt*2],   ah[mf], bh4[0], bh4[1]);
                    mma_f16(acc[mf][nt*2],   as[mf], bl4[0], bl4[1]);
                    mma_f16(acc[mf][nt*2+1], ah[mf], bh4[2], bh4[3]);
                    mma_f16(acc[mf][nt*2+1], as[mf], bl4[2], bl4[3]);
                }
            }
        }
    }

    // ---- epilogue ----
    #pragma unroll
    for (int mf = 0; mf < 4; mf++) {
        #pragma unroll
        for (int nf = 0; nf < 4; nf++) {
            int col = bn + wn * 32 + nf * 8 + (lane & 3) * 2;
            float2 bv = *(const float2*)(bias + col);
            #pragma unroll
            for (int half = 0; half < 2; half++) {
                int row = bm + wm * 64 + mf * 16 + (lane >> 2) + half * 8;
                float v0 = acc[mf][nf][half * 2 + 0] + bv.x;
                float v1 = acc[mf][nf][half * 2 + 1] + bv.y;
                if (EPI == 1) {
                    v0 = gelu_f(v0); v1 = gelu_f(v1);
                    *(uint32_t*)(outh + (size_t)row * N + col) = pack_h(v0, v1);
                } else if (EPI == 3) {
                    int sector = col >> 10;
                    int wcol = col & 1023;
                    int hh = wcol >> 6;
                    int dd = wcol & 63;
                    int brow = row >> 11;
                    int lrow = row & 2047;
                    size_t dst = ((size_t)(brow * Hx + hh) * Lx + lrow) * Dx + dd;
                    if (sector == 0) {
                        *(uint32_t*)(q_ + dst) = pack_h(v0 * 0.125f, v1 * 0.125f);
                    } else if (sector == 1) {
                        *(uint32_t*)(kh_  + dst) = pack_h(v0, v1);
                        *(uint32_t*)(kls_ + dst) = pack_ls(v0, v1);
                    } else {
                        *(uint32_t*)(vh_  + dst) = pack_h(v0, v1);
                        *(uint32_t*)(vls_ + dst) = pack_ls(v0, v1);
                    }
                } else {
                    float2 rv = *(const float2*)(res + (size_t)row * N + col);
                    v0 += rv.x; v1 += rv.y;
                    *(float2*)(outf + (size_t)row * N + col) = make_float2(v0, v1);
                }
            }
        }
    }
}

// ---------------- LayerNorm -> fp16 output --------------------------------
__global__ __launch_bounds__(256) void ln_kernel(const float* __restrict__ x,
                                                 const float* __restrict__ w,
                                                 const float* __restrict__ b,
                                                 __half* __restrict__ oh)
{
    int row = blockIdx.x;
    int t   = threadIdx.x;
    const float4* xr = (const float4*)(x + (size_t)row * Cx);
    float4 v = xr[t];
    float s  = v.x + v.y + v.z + v.w;
    float sq = v.x*v.x + v.y*v.y + v.z*v.z + v.w*v.w;
    #pragma unroll
    for (int o = 16; o > 0; o >>= 1) {
        s  += __shfl_xor_sync(0xffffffffu, s,  o);
        sq += __shfl_xor_sync(0xffffffffu, sq, o);
    }
    __shared__ float ss[8], ssq[8];
    int wid = t >> 5, lane = t & 31;
    if (lane == 0) { ss[wid] = s; ssq[wid] = sq; }
    __syncthreads();
    float tot = 0.f, totq = 0.f;
    #pragma unroll
    for (int i = 0; i < 8; i++) { tot += ss[i]; totq += ssq[i]; }
    float mean = tot * (1.0f / Cx);
    float var  = totq * (1.0f / Cx) - mean * mean;
    float rstd = rsqrtf(var + 1e-5f);
    const float4 wv = ((const float4*)w)[t];
    const float4 bv = ((const float4*)b)[t];
    float o0 = (v.x - mean) * rstd * wv.x + bv.x;
    float o1 = (v.y - mean) * rstd * wv.y + bv.y;
    float o2 = (v.z - mean) * rstd * wv.z + bv.z;
    float o3 = (v.w - mean) * rstd * wv.w + bv.w;
    size_t idx = (size_t)row * Cx + t * 4;
    *(uint2*)(oh + idx) = make_uint2(pack_h(o0, o1), pack_h(o2, o3));
}

// =========================================================================
// Tensor-core causal flash attention, 2-term split-fp16.
// 128 threads (4 warps), 64 q-rows per CTA, 2-stage KV ring -> 2 CTAs/SM.
// grid (Lx/64, Bsz*Hx).
// =========================================================================
#define QSTR 144
#define ATT_QS   9216             // 64*144 (Q region)
#define ATT_KVS  9216             // one array (64 rows x 144B)
#define ATT_STG  (4*ATT_KVS)      // 36864
#define ATT_SMEM (ATT_QS + 2*ATT_STG)  // 82944 -> 2 CTAs/SM

__global__ __launch_bounds__(128, 2) void attn_mma(
    const __half* __restrict__ q_,
    const __half* __restrict__ kh_, const __half* __restrict__ kls_,
    const __half* __restrict__ vh_, const __half* __restrict__ vls_,
    __half* __restrict__ y_)
{
    extern __shared__ char sm_raw[];
    const uint32_t S = smem_u32(sm_raw);
    const int tid = threadIdx.x, wid = tid >> 5, lane = tid & 31;
    const int qt  = gridDim.x - 1 - blockIdx.x;   // heavy CTAs first
    const int qb  = qt * 64;
    const int bh  = blockIdx.y;
    const size_t hb = (size_t)bh * Lx * Dx;

    const __half *Q  = q_  + hb;
    const __half *Kh = kh_ + hb, *Kl = kls_ + hb;
    const __half *Vh = vh_ + hb, *Vl = vls_ + hb;

    const int nk = qt + 1;

    auto load_kv = [&](int kt) {
        if (kt < nk) {
            const uint32_t db = S + ATT_QS + (kt & 1) * ATT_STG;
            #pragma unroll
            for (int u = 0; u < 16; u++) {
                int j = u * 128 + tid;
                int arr = j >> 9;
                int rem = j & 511;
                int row = rem >> 3, seg = rem & 7;
                const __half* src = (arr == 0) ? Kh : (arr == 1) ? Kl
                                   : (arr == 2) ? Vh : Vl;
                cp16(db + arr * ATT_KVS + row * QSTR + seg * 16,
                     src + (size_t)(kt * 64 + row) * Dx + seg * 8);
            }
        }
        CP_COMMIT();
    };

    // prologue: one group = {Q, kv0}
    #pragma unroll
    for (int u = 0; u < 4; u++) {
        int j = u * 128 + tid;
        int row = j >> 3, seg = j & 7;
        cp16(S + row * QSTR + seg * 16,
             Q + (size_t)(qb + row) * Dx + seg * 8);
    }
    {
        const uint32_t db = S + ATT_QS;
        #pragma unroll
        for (int u = 0; u < 16; u++) {
            int j = u * 128 + tid;
            int arr = j >> 9;
            int rem = j & 511;
            int row = rem >> 3, seg = rem & 7;
            const __half* src = (arr == 0) ? Kh : (arr == 1) ? Kl
                               : (arr == 2) ? Vh : Vl;
            cp16(db + arr * ATT_KVS + row * QSTR + seg * 16,
                 src + (size_t)row * Dx + seg * 8);
        }
        CP_COMMIT();
    }

    uint32_t qf[4][4], qs[4][4];
    float oc[8][4];
    #pragma unroll
    for (int d = 0; d < 8; d++)
        #pragma unroll
        for (int i = 0; i < 4; i++) oc[d][i] = 0.f;
    float m0 = -1e30f, m1 = -1e30f, l0 = 0.f, l1 = 0.f;

    const int wrow_min = qb + wid * 16;
    const int r0g = wrow_min + (lane >> 2);

    for (int kt = 0; kt < nk; kt++) {
        CP_WAIT0();              // kv kt (issued one iter ago) landed
        __syncthreads();         // all warps done with tile kt-1
        if (kt == 0) {
            #pragma unroll
            for (int ks = 0; ks < 4; ks++) {
                uint32_t ao = S + (wid * 16 + (lane & 15)) * QSTR
                            + (lane >> 4) * 16 + ks * 32;
                ldsm4(qf[ks], ao);
                #pragma unroll
                for (int r = 0; r < 4; r++) qs[ks][r] = hscale(qf[ks][r]);
            }
        }
        load_kv(kt + 1);         // writes stage (kt+1)&1, reused from kt-1: safe

        const int k0 = kt * 64;
        const uint32_t kb = S + ATT_QS + (kt & 1) * ATT_STG;

        // ---- S = Q @ K^T (2-term) ----
        float sc[8][4];
        #pragma unroll
        for (int nt = 0; nt < 8; nt++)
            #pragma unroll
            for (int i = 0; i < 4; i++) sc[nt][i] = 0.f;

        #pragma unroll
        for (int ks = 0; ks < 4; ks++) {
            uint32_t k4[4][4], kl4[4][4];
            #pragma unroll
            for (int ntp = 0; ntp < 4; ntp++) {
                uint32_t ad = kb
                    + (uint32_t)((ntp * 16 + (lane & 7) + ((lane >> 4) << 3)) * QSTR)
                    + ((lane >> 3) & 1) * 16 + ks * 32;
                ldsm4(k4[ntp], ad);
                ldsm4(kl4[ntp], ad + ATT_KVS);
            }
            #pragma unroll
            for (int ntp = 0; ntp < 4; ntp++)
                #pragma unroll
                for (int hf = 0; hf < 2; hf++) {
                    int nt = ntp * 2 + hf, p = hf * 2;
                    mma_f16(sc[nt], qf[ks], k4[ntp][p],  k4[ntp][p + 1]);
                    mma_f16(sc[nt], qs[ks], kl4[ntp][p], kl4[ntp][p + 1]);
                }
        }

        // ---- causal mask (diagonal tile only) ----
        if (kt == qt) {
            #pragma unroll
            for (int nt = 0; nt < 8; nt++) {
                int key = k0 + nt * 8 + (lane & 3) * 2;
                if (key     > r0g)     sc[nt][0] = -1e30f;
                if (key + 1 > r0g)     sc[nt][1] = -1e30f;
                if (key     > r0g + 8) sc[nt][2] = -1e30f;
                if (key + 1 > r0g + 8) sc[nt][3] = -1e30f;
            }
        }

        // ---- online softmax ----
        float rm0 = -1e30f, rm1 = -1e30f;
        #pragma unroll
        for (int nt = 0; nt < 8; nt++) {
            rm0 = fmaxf(rm0, fmaxf(sc[nt][0], sc[nt][1]));
            rm1 = fmaxf(rm1, fmaxf(sc[nt][2], sc[nt][3]));
        }
        rm0 = fmaxf(rm0, __shfl_xor_sync(0xffffffffu, rm0, 1));
        rm0 = fmaxf(rm0, __shfl_xor_sync(0xffffffffu, rm0, 2));
        rm1 = fmaxf(rm1, __shfl_xor_sync(0xffffffffu, rm1, 1));
        rm1 = fmaxf(rm1, __shfl_xor_sync(0xffffffffu, rm1, 2));
        float mn0 = fmaxf(m0, rm0 * LOG2E);
        float mn1 = fmaxf(m1, rm1 * LOG2E);
        float s0 = pexp2(m0 - mn0);
        float s1 = pexp2(m1 - mn1);
        m0 = mn0; m1 = mn1;
        l0 *= s0; l1 *= s1;
        #pragma unroll
        for (int d = 0; d < 8; d++) {
            oc[d][0] *= s0; oc[d][1] *= s0;
            oc[d][2] *= s1; oc[d][3] *= s1;
        }

        uint32_t pa[4][4], pas[4][4];
        float la0 = 0.f, la1 = 0.f;
        #pragma unroll
        for (int nt = 0; nt < 8; nt++) {
            float p0 = pexp2(fmaf(sc[nt][0], LOG2E, -m0));
            float p1 = pexp2(fmaf(sc[nt][1], LOG2E, -m0));
            float p2 = pexp2(fmaf(sc[nt][2], LOG2E, -m1));
            float p3 = pexp2(fmaf(sc[nt][3], LOG2E, -m1));
            la0 += p0 + p1;
            la1 += p2 + p3;
            int ks2 = nt >> 1, idx = (nt & 1) * 2;
            pa[ks2][idx]     = pack_h(p0, p1);
            pa[ks2][idx + 1] = pack_h(p2, p3);
        }
        l0 += la0; l1 += la1;
        #pragma unroll
        for (int ks2 = 0; ks2 < 4; ks2++)
            #pragma unroll
            for (int r = 0; r < 4; r++) pas[ks2][r] = hscale(pa[ks2][r]);

        // ---- O += P @ V (2-term) ----
        #pragma unroll
        for (int ks2 = 0; ks2 < 4; ks2++) {
            uint32_t v4[4][4], vl4[4][4];
            #pragma unroll
            for (int dtp = 0; dtp < 4; dtp++) {
                uint32_t ad = kb + 2 * ATT_KVS
                    + (uint32_t)((ks2 * 16 + (lane & 15)) * QSTR)
                    + (dtp * 16 + (lane >> 4) * 8) * 2;
                ldsm4t(v4[dtp], ad);
                ldsm4t(vl4[dtp], ad + ATT_KVS);
            }
            #pragma unroll
            for (int dtp = 0; dtp < 4; dtp++)
                #pragma unroll
                for (int hf = 0; hf < 2; hf++) {
                    int dt = dtp * 2 + hf, p = hf * 2;
                    mma_f16(oc[dt], pa[ks2],  v4[dtp][p],  v4[dtp][p + 1]);
                    mma_f16(oc[dt], pas[ks2], vl4[dtp][p], vl4[dtp][p + 1]);
                }
        }
    }

    // ---- finalize ----
    l0 += __shfl_xor_sync(0xffffffffu, l0, 1);
    l0 += __shfl_xor_sync(0xffffffffu, l0, 2);
    l1 += __shfl_xor_sync(0xffffffffu, l1, 1);
    l1 += __shfl_xor_sync(0xffffffffu, l1, 2);
    float i0 = 1.f / l0, i1 = 1.f / l1;

    const int b  = bh >> 4;
    const int hh = bh & 15;
    const size_t row0 = (size_t)b * Lx + qb + wid * 16 + (lane >> 2);
    const int colb = hh * 64 + (lane & 3) * 2;
    #pragma unroll
    for (int dt = 0; dt < 8; dt++) {
        float a0 = oc[dt][0] * i0, a1 = oc[dt][1] * i0;
        float a2 = oc[dt][2] * i1, a3 = oc[dt][3] * i1;
        *(uint32_t*)(y_ + row0 * Cx + colb + dt * 8)       = pack_h(a0, a1);
        *(uint32_t*)(y_ + (row0 + 8) * Cx + colb + dt * 8) = pack_h(a2, a3);
    }
}

// ---------------- launcher ----------------
extern "C" void kernel_launch(void* const* d_in, const int* in_sizes, int n_in,
                              void* d_out, int out_size)
{
    const float* x      = (const float*)d_in[0];
    const float* ln1_w  = (const float*)d_in[1];
    const float* ln1_b  = (const float*)d_in[2];
    const float* w_attn = (const float*)d_in[3];
    const float* b_attn = (const float*)d_in[4];
    const float* w_proj = (const float*)d_in[5];
    const float* b_proj = (const float*)d_in[6];
    const float* ln2_w  = (const float*)d_in[7];
    const float* ln2_b  = (const float*)d_in[8];
    const float* w_fc   = (const float*)d_in[9];
    const float* b_fc   = (const float*)d_in[10];
    const float* w_fc2  = (const float*)d_in[11];
    const float* b_fc2  = (const float*)d_in[12];
    float* out = (float*)d_out;

    void *px1, *ph, *py, *pfc, *pq, *pkh, *pkl, *pvh, *pvl;
    void *pwah, *pwal, *pwph, *pwpl, *pwfh, *pwfl, *pw2h, *pw2l;
    cudaGetSymbolAddress(&px1, g_x1);
    cudaGetSymbolAddress(&ph,  g_h);
    cudaGetSymbolAddress(&py,  g_y);
    cudaGetSymbolAddress(&pfc, g_fc);
    cudaGetSymbolAddress(&pq,  g_q);
    cudaGetSymbolAddress(&pkh, g_kh);  cudaGetSymbolAddress(&pkl, g_kls);
    cudaGetSymbolAddress(&pvh, g_vh);  cudaGetSymbolAddress(&pvl, g_vls);
    cudaGetSymbolAddress(&pwah, g_wa_h); cudaGetSymbolAddress(&pwal, g_wa_l);
    cudaGetSymbolAddress(&pwph, g_wp_h); cudaGetSymbolAddress(&pwpl, g_wp_l);
    cudaGetSymbolAddress(&pwfh, g_wf_h); cudaGetSymbolAddress(&pwfl, g_wf_l);
    cudaGetSymbolAddress(&pw2h, g_w2_h); cudaGetSymbolAddress(&pw2l, g_w2_l);

    float* x1 = (float*)px1;
    __half* h  = (__half*)ph;
    __half* y  = (__half*)py;
    __half* fc = (__half*)pfc;
    __half* q  = (__half*)pq;
    __half *kh = (__half*)pkh, *kl = (__half*)pkl;
    __half *vh = (__half*)pvh, *vl = (__half*)pvl;
    __half *wah = (__half*)pwah, *wal = (__half*)pwal;
    __half *wph = (__half*)pwph, *wpl = (__half*)pwpl;
    __half *wfh = (__half*)pwfh, *wfl = (__half*)pwfl;
    __half *w2h = (__half*)pw2h, *w2l = (__half*)pw2l;

    static bool attr_done = false;
    if (!attr_done) {
        cudaFuncSetAttribute(mma_gemm<1>, cudaFuncAttributeMaxDynamicSharedMemorySize, GEMM_SMEM);
        cudaFuncSetAttribute(mma_gemm<2>, cudaFuncAttributeMaxDynamicSharedMemorySize, GEMM_SMEM);
        cudaFuncSetAttribute(mma_gemm<3>, cudaFuncAttributeMaxDynamicSharedMemorySize, GEMM_SMEM);
        cudaFuncSetAttribute(attn_mma,    cudaFuncAttributeMaxDynamicSharedMemorySize, ATT_SMEM);
        attr_done = true;
    }

    // 0) weight pre-conversion
    conv_all<<<(N4_TOT + 255)/256, 256>>>(w_attn, w_proj, w_fc, w_fc2);

    // 1) h = LN1(x)
    ln_kernel<<<Mrows, 256>>>(x, ln1_w, ln1_b, h);
    // 2) QKV GEMM -> q (fp16, x0.125) / k,v (hi+ls), [B,H,L,D]
    mma_gemm<3><<<dim3(3*Cx/128, Mrows/128), 256, GEMM_SMEM>>>(
        h, wah, wal, b_attn, nullptr, nullptr, nullptr,
        q, kh, kl, vh, vl, Mrows, 3*Cx, Cx);
    // 3) y = causal flash attention (64 q-rows/CTA, 2 CTAs/SM)
    attn_mma<<<dim3(Lx/64, Bsz*Hx), 128, ATT_SMEM>>>(q, kh, kl, vh, vl, y);
    // 4) x1 = x + y @ w_proj + b_proj
    mma_gemm<2><<<dim3(Cx/128, Mrows/128), 256, GEMM_SMEM>>>(
        y, wph, wpl, b_proj, x, x1, nullptr,
        nullptr, nullptr, nullptr, nullptr, nullptr, Mrows, Cx, Cx);
    // 5) h = LN2(x1)
    ln_kernel<<<Mrows, 256>>>(x1, ln2_w, ln2_b, h);
    // 6) fc = gelu(h @ w_fc + b_fc) -> fp16
    mma_gemm<1><<<dim3(4*Cx/128, Mrows/128), 256, GEMM_SMEM>>>(
        h, wfh, wfl, b_fc, nullptr, nullptr, fc,
        nullptr, nullptr, nullptr, nullptr, nullptr, Mrows, 4*Cx, Cx);
    // 7) out = x1 + fc @ w_fc2 + b_fc2
    mma_gemm<2><<<dim3(Cx/128, Mrows/128), 256, GEMM_SMEM>>>(
        fc, w2h, w2l, b_fc2, x1, out, nullptr,
        nullptr, nullptr, nullptr, nullptr, nullptr, Mrows, Cx, 4*Cx);
}